// round 2
// baseline (speedup 1.0000x reference)
#include <cuda_runtime.h>
#include <math.h>

#define NN   50000
#define EE   400000
#define FIN  128
#define HID  64
#define HEADS 4
#define NCLS 121
#define M1   256   // HEADS*HID
#define M3   484   // OUT_HEADS*NCLS

// ---------------- scratch (static device globals; no allocation) ----------------
__device__ float g_xh [(size_t)NN * M3];   // per-layer transformed features [N, M]
__device__ float g_agg[(size_t)NN * M3];   // per-layer aggregation output   [N, M]
__device__ float g_lin[(size_t)NN * M1];   // linear-skip outputs (lin1 / lin3)
__device__ float g_h  [(size_t)NN * M1];   // hidden features h1 / h2
__device__ float g_as [NN * HEADS];
__device__ float g_ad [NN * HEADS];
__device__ float g_m  [NN * HEADS];
__device__ float g_den[NN * HEADS];

// ---------------- helpers ----------------
__device__ __forceinline__ void atomicMaxF(float* addr, float v) {
    // monotone int/uint trick; valid for all non-NaN floats incl. -inf
    if (v >= 0.f) atomicMax((int*)addr, __float_as_int(v));
    else          atomicMin((unsigned int*)addr, __float_as_uint(v));
}

__global__ void fill_f(float* p, float v, long n) {
    long i = blockIdx.x * (long)blockDim.x + threadIdx.x;
    long stride = (long)gridDim.x * blockDim.x;
    for (; i < n; i += stride) p[i] = v;
}

// ---------------- SGEMM: C[N x M] = A[N x K] @ B[K x M], row-major, K % 16 == 0 ----------------
#define BM 128
#define BN 64
#define BK 16
#define TM 8
#define TN 4
__global__ __launch_bounds__(256) void sgemm(const float* __restrict__ A,
                                             const float* __restrict__ B,
                                             float* __restrict__ C,
                                             int Nrows, int K, int M) {
    __shared__ float As[BK][BM + 4];
    __shared__ float Bs[BK][BN];
    int tid = threadIdx.x;
    int tx = tid & 15;        // 0..15 -> cols
    int ty = tid >> 4;        // 0..15 -> rows
    int rowBase = blockIdx.y * BM;
    int colBase = blockIdx.x * BN;

    float acc[TM][TN];
#pragma unroll
    for (int i = 0; i < TM; i++)
#pragma unroll
        for (int j = 0; j < TN; j++) acc[i][j] = 0.f;

    for (int k0 = 0; k0 < K; k0 += BK) {
        // load A tile: BM x BK (2048 elems / 256 thr = 8 each)
#pragma unroll
        for (int l = 0; l < (BM * BK) / 256; l++) {
            int idx = tid + l * 256;
            int r = idx / BK, c = idx % BK;
            int gr = rowBase + r;
            As[c][r] = (gr < Nrows) ? A[(size_t)gr * K + (k0 + c)] : 0.f;
        }
        // load B tile: BK x BN (1024 elems / 256 thr = 4 each)
#pragma unroll
        for (int l = 0; l < (BK * BN) / 256; l++) {
            int idx = tid + l * 256;
            int r = idx / BN, c = idx % BN;
            int gc = colBase + c;
            Bs[r][c] = (gc < M) ? B[(size_t)(k0 + r) * M + gc] : 0.f;
        }
        __syncthreads();
#pragma unroll
        for (int k = 0; k < BK; k++) {
            float a[TM], b[TN];
#pragma unroll
            for (int i = 0; i < TM; i++) a[i] = As[k][ty * TM + i];
#pragma unroll
            for (int j = 0; j < TN; j++) b[j] = Bs[k][tx * TN + j];
#pragma unroll
            for (int i = 0; i < TM; i++)
#pragma unroll
                for (int j = 0; j < TN; j++) acc[i][j] += a[i] * b[j];
        }
        __syncthreads();
    }
#pragma unroll
    for (int i = 0; i < TM; i++) {
        int gr = rowBase + ty * TM + i;
        if (gr >= Nrows) continue;
#pragma unroll
        for (int j = 0; j < TN; j++) {
            int gc = colBase + tx * TN + j;
            if (gc < M) C[(size_t)gr * M + gc] = acc[i][j];
        }
    }
}

// ---------------- alpha_s / alpha_d: warp per (node, head) ----------------
__global__ void alpha_kernel(const float* __restrict__ xh,
                             const float* __restrict__ asrc,
                             const float* __restrict__ adst,
                             float* __restrict__ as_, float* __restrict__ ad_,
                             int H, int C) {
    int w    = (blockIdx.x * blockDim.x + threadIdx.x) >> 5;
    int lane = threadIdx.x & 31;
    if (w >= NN * H) return;
    int n = w / H, h = w - n * H;
    const float* row = xh + (size_t)n * (H * C) + h * C;
    const float* w1  = asrc + h * C;
    const float* w2  = adst + h * C;
    float s1 = 0.f, s2 = 0.f;
    for (int c = lane; c < C; c += 32) {
        float v = row[c];
        s1 += v * w1[c];
        s2 += v * w2[c];
    }
#pragma unroll
    for (int o = 16; o; o >>= 1) {
        s1 += __shfl_down_sync(0xffffffffu, s1, o);
        s2 += __shfl_down_sync(0xffffffffu, s2, o);
    }
    if (lane == 0) { as_[w] = s1; ad_[w] = s2; }
}

// ---------------- edge passes ----------------
__global__ void edge_max(const int* __restrict__ ei,
                         const float* __restrict__ as_, const float* __restrict__ ad_,
                         float* __restrict__ m_, int H) {
    int i = blockIdx.x * blockDim.x + threadIdx.x;
    if (i >= EE * H) return;
    int e = i / H, h = i - e * H;
    int src = ei[e], dst = ei[EE + e];
    float lg = as_[src * H + h] + ad_[dst * H + h];
    lg = lg > 0.f ? lg : 0.2f * lg;
    atomicMaxF(&m_[dst * H + h], lg);
}

__global__ void edge_sum(const int* __restrict__ ei,
                         const float* __restrict__ as_, const float* __restrict__ ad_,
                         const float* __restrict__ m_, float* __restrict__ den_, int H) {
    int i = blockIdx.x * blockDim.x + threadIdx.x;
    if (i >= EE * H) return;
    int e = i / H, h = i - e * H;
    int src = ei[e], dst = ei[EE + e];
    float lg = as_[src * H + h] + ad_[dst * H + h];
    lg = lg > 0.f ? lg : 0.2f * lg;
    atomicAdd(&den_[dst * H + h], expf(lg - m_[dst * H + h]));
}

// warp per (edge, head): alpha recomputed, channels scattered with atomicAdd
__global__ void aggregate(const int* __restrict__ ei,
                          const float* __restrict__ xh,
                          const float* __restrict__ as_, const float* __restrict__ ad_,
                          const float* __restrict__ m_, const float* __restrict__ den_,
                          float* __restrict__ out, int H, int C) {
    int w    = (blockIdx.x * blockDim.x + threadIdx.x) >> 5;
    int lane = threadIdx.x & 31;
    if (w >= EE * H) return;
    int e = w / H, h = w - e * H;
    int src = ei[e], dst = ei[EE + e];
    float lg = as_[src * H + h] + ad_[dst * H + h];
    lg = lg > 0.f ? lg : 0.2f * lg;
    float alpha = expf(lg - m_[dst * H + h]) / (den_[dst * H + h] + 1e-16f);
    const float* xr   = xh  + (size_t)src * (H * C) + h * C;
    float*       orow = out + (size_t)dst * (H * C) + h * C;
    for (int c = lane; c < C; c += 32)
        atomicAdd(&orow[c], alpha * xr[c]);
}

// ---------------- finalize kernels ----------------
__global__ void final1(const float* __restrict__ agg, const float* __restrict__ b1,
                       const float* __restrict__ lin, const float* __restrict__ lin1b,
                       float* __restrict__ h) {
    long i = blockIdx.x * (long)blockDim.x + threadIdx.x;
    if (i >= (long)NN * M1) return;
    int j = (int)(i % M1);
    float v = agg[i] + b1[j] + lin[i] + lin1b[j];
    h[i] = v > 0.f ? v : expm1f(v);
}

__global__ void final2(const float* __restrict__ agg, const float* __restrict__ b2,
                       float* __restrict__ h) {
    long i = blockIdx.x * (long)blockDim.x + threadIdx.x;
    if (i >= (long)NN * M1) return;
    int j = (int)(i % M1);
    float v = agg[i] + b2[j] + h[i];
    h[i] = v > 0.f ? v : expm1f(v);
}

__global__ void final3(const float* __restrict__ agg, const float* __restrict__ b3,
                       const float* __restrict__ lin, const float* __restrict__ lin3b,
                       float* __restrict__ out) {
    long i = blockIdx.x * (long)blockDim.x + threadIdx.x;
    if (i >= (long)NN * NCLS) return;
    int n = (int)(i / NCLS), k = (int)(i % NCLS);
    const float* ar = agg + (size_t)n * M3;
    float s = 0.25f * (ar[k] + ar[NCLS + k] + ar[2 * NCLS + k] + ar[3 * NCLS + k]);
    out[i] = s + b3[k] + lin[i] + lin3b[k];
}

// ---------------- host orchestration ----------------
static void run_gat(const float* X, int K, const float* W,
                    const float* asrc, const float* adst,
                    int H, int C, const int* ei,
                    float* xh, float* agg, float* as_, float* ad_,
                    float* m_, float* den_) {
    int M = H * C;
    dim3 gg((M + BN - 1) / BN, (NN + BM - 1) / BM);
    sgemm<<<gg, 256>>>(X, W, xh, NN, K, M);

    alpha_kernel<<<(NN * H * 32 + 255) / 256, 256>>>(xh, asrc, adst, as_, ad_, H, C);

    fill_f<<<256, 256>>>(m_, -INFINITY, (long)NN * H);
    fill_f<<<256, 256>>>(den_, 0.f, (long)NN * H);
    fill_f<<<4096, 256>>>(agg, 0.f, (long)NN * M);

    edge_max<<<(EE * H + 255) / 256, 256>>>(ei, as_, ad_, m_, H);
    edge_sum<<<(EE * H + 255) / 256, 256>>>(ei, as_, ad_, m_, den_, H);
    aggregate<<<((long)EE * H * 32 + 255) / 256, 256>>>(ei, xh, as_, ad_, m_, den_, agg, H, C);
}

extern "C" void kernel_launch(void* const* d_in, const int* in_sizes, int n_in,
                              void* d_out, int out_size) {
    const float* x      = (const float*)d_in[0];
    const int*   ei     = (const int*)  d_in[1];
    const float* W1     = (const float*)d_in[2];
    const float* a1s    = (const float*)d_in[3];
    const float* a1d    = (const float*)d_in[4];
    const float* b1     = (const float*)d_in[5];
    const float* lin1W  = (const float*)d_in[6];
    const float* lin1b  = (const float*)d_in[7];
    const float* W2     = (const float*)d_in[8];
    const float* a2s    = (const float*)d_in[9];
    const float* a2d    = (const float*)d_in[10];
    const float* b2     = (const float*)d_in[11];
    const float* W3     = (const float*)d_in[12];
    const float* a3s    = (const float*)d_in[13];
    const float* a3d    = (const float*)d_in[14];
    const float* b3     = (const float*)d_in[15];
    const float* lin3W  = (const float*)d_in[16];
    const float* lin3b  = (const float*)d_in[17];
    float* out = (float*)d_out;

    float *xh, *agg, *lin, *h, *as_, *ad_, *m_, *den_;
    cudaGetSymbolAddress((void**)&xh,  g_xh);
    cudaGetSymbolAddress((void**)&agg, g_agg);
    cudaGetSymbolAddress((void**)&lin, g_lin);
    cudaGetSymbolAddress((void**)&h,   g_h);
    cudaGetSymbolAddress((void**)&as_, g_as);
    cudaGetSymbolAddress((void**)&ad_, g_ad);
    cudaGetSymbolAddress((void**)&m_,  g_m);
    cudaGetSymbolAddress((void**)&den_, g_den);

    // ---- layer 1: h1 = elu(GAT1(x) + b1 + x@lin1_W + lin1_b) ----
    run_gat(x, FIN, W1, a1s, a1d, HEADS, HID, ei, xh, agg, as_, ad_, m_, den_);
    {
        dim3 gg((M1 + BN - 1) / BN, (NN + BM - 1) / BM);
        sgemm<<<gg, 256>>>(x, lin1W, lin, NN, FIN, M1);
    }
    final1<<<((long)NN * M1 + 255) / 256, 256>>>(agg, b1, lin, lin1b, h);

    // ---- layer 2: h2 = elu(GAT2(h1) + b2 + h1) ----
    run_gat(h, M1, W2, a2s, a2d, HEADS, HID, ei, xh, agg, as_, ad_, m_, den_);
    final2<<<((long)NN * M1 + 255) / 256, 256>>>(agg, b2, h);

    // ---- layer 3: out = mean_heads(GAT3(h2)) + b3 + h2@lin3_W + lin3_b ----
    run_gat(h, M1, W3, a3s, a3d, HEADS, NCLS, ei, xh, agg, as_, ad_, m_, den_);
    {
        dim3 gg((NCLS + BN - 1) / BN, (NN + BM - 1) / BM);
        sgemm<<<gg, 256>>>(h, lin3W, lin, NN, M1, NCLS);
    }
    final3<<<((long)NN * NCLS + 255) / 256, 256>>>(agg, b3, lin, lin3b, out);

    (void)in_sizes; (void)n_in; (void)out_size;
}

// round 4
// speedup vs baseline: 1.0044x; 1.0044x over previous
#include <cuda_runtime.h>
#include <cuda_bf16.h>
#include <math.h>
#include <stdint.h>

#define NN   50000
#define EE   400000
#define FIN  128
#define HID  64
#define HEADS 4
#define NCLS 121
#define M1   256   // HEADS*HID
#define M3   484   // OUT_HEADS*NCLS

// ---------------- scratch (static device globals; no allocation) ----------------
__device__ float g_xh [(size_t)NN * M3];   // transformed features [N, M]
__device__ float g_agg[(size_t)NN * M3];   // aggregation output   [N, M]
__device__ float g_lin[(size_t)NN * M1];   // linear-skip outputs
__device__ float g_h  [(size_t)NN * M1];   // hidden features h1 / h2
__device__ float g_as [NN * HEADS];
__device__ float g_ad [NN * HEADS];
__device__ float g_m  [NN * HEADS];
__device__ float g_den[NN * HEADS];
__device__ __nv_bfloat16 g_Ah[(size_t)50048 * 768]; // A' = [Xh | Xh | Xl], padded rows
__device__ __nv_bfloat16 g_Bt[(size_t)512 * 768];   // B' transposed = [Wh | Wl | Wh]

// ---------------- bf16 hi/lo conversion kernels ----------------
// A' layout: [Nrows, 3K] bf16 : cols [0,K)=hi(x), [K,2K)=hi(x), [2K,3K)=lo(x)
__global__ void convA(const float* __restrict__ X, __nv_bfloat16* __restrict__ Ap, int Nrows, int K) {
    long i = blockIdx.x * (long)blockDim.x + threadIdx.x;
    long tot = (long)Nrows * K;
    long stride = (long)gridDim.x * blockDim.x;
    for (; i < tot; i += stride) {
        int r = (int)(i / K), k = (int)(i - (long)r * K);
        float x = X[i];
        __nv_bfloat16 h = __float2bfloat16(x);
        __nv_bfloat16 l = __float2bfloat16(x - __bfloat162float(h));
        __nv_bfloat16* row = Ap + (size_t)r * (3 * K);
        row[k] = h; row[K + k] = h; row[2 * K + k] = l;
    }
}
// B' layout: [Npad, 3K] bf16 : row n = [hi(W[:,n]) | lo(W[:,n]) | hi(W[:,n])]; n>=M -> 0
__global__ void convB(const float* __restrict__ W, __nv_bfloat16* __restrict__ Bp, int K, int M, int Npad) {
    long i = blockIdx.x * (long)blockDim.x + threadIdx.x;
    long tot = (long)Npad * K;
    if (i >= tot) return;
    int n = (int)(i / K), k = (int)(i - (long)n * K);
    float w = (n < M) ? W[(size_t)k * M + n] : 0.f;
    __nv_bfloat16 h = __float2bfloat16(w);
    __nv_bfloat16 l = __float2bfloat16(w - __bfloat162float(h));
    __nv_bfloat16* row = Bp + (size_t)n * (3 * K);
    row[k] = h; row[K + k] = l; row[2 * K + k] = h;
}

// ---------------- HMMA GEMM: C[Nrows x Nout] = A'[Nrows x Kp] . B'[Npad x Kp]^T ----------------
// mma.sync.m16n8k16 bf16 -> f32. Tile 128x128x32, 256 thr = 2(m) x 4(n) warps, warp tile 64x32.
#define APITCH 17   // b32 pitch for 16 b32 (32 bf16) rows; 17 coprime with 32 banks

__global__ __launch_bounds__(256) void gemm_mma(const __nv_bfloat16* __restrict__ A,
                                                const __nv_bfloat16* __restrict__ Bt,
                                                float* __restrict__ C,
                                                int Nrows, int Kp, int Nout) {
    __shared__ uint32_t As[128 * APITCH];
    __shared__ uint32_t Bs[128 * APITCH];
    int tid  = threadIdx.x;
    int wid  = tid >> 5, lane = tid & 31;
    int wm   = wid & 1;          // 0..1 -> 64-row slab
    int wn   = wid >> 1;         // 0..3 -> 32-col slab
    int g    = lane >> 2;        // 0..7
    int tg   = lane & 3;         // 0..3
    int rowBase = blockIdx.y * 128;
    int colBase = blockIdx.x * 128;

    float acc[4][4][4];
#pragma unroll
    for (int i = 0; i < 4; i++)
#pragma unroll
        for (int j = 0; j < 4; j++)
#pragma unroll
            for (int q = 0; q < 4; q++) acc[i][j][q] = 0.f;

    int lr   = tid >> 1;      // 0..127 : tile row to load
    int half = tid & 1;       // 16-bf16 half

    for (int k0 = 0; k0 < Kp; k0 += 32) {
        // ---- load A tile (128 x 32 bf16) ----
        {
            int grow = rowBase + lr;
            uint4 v0 = make_uint4(0, 0, 0, 0), v1 = v0;
            if (grow < Nrows) {
                const uint4* p = (const uint4*)(A + (size_t)grow * Kp + k0 + half * 16);
                v0 = p[0]; v1 = p[1];
            }
            uint32_t* d = As + lr * APITCH + half * 8;
            d[0] = v0.x; d[1] = v0.y; d[2] = v0.z; d[3] = v0.w;
            d[4] = v1.x; d[5] = v1.y; d[6] = v1.z; d[7] = v1.w;
        }
        // ---- load B tile (128 x 32 bf16), rows always valid (padded) ----
        {
            const uint4* p = (const uint4*)(Bt + (size_t)(colBase + lr) * Kp + k0 + half * 16);
            uint4 v0 = p[0], v1 = p[1];
            uint32_t* d = Bs + lr * APITCH + half * 8;
            d[0] = v0.x; d[1] = v0.y; d[2] = v0.z; d[3] = v0.w;
            d[4] = v1.x; d[5] = v1.y; d[6] = v1.z; d[7] = v1.w;
        }
        __syncthreads();

#pragma unroll
        for (int ks = 0; ks < 2; ks++) {
            int kb = ks * 8;  // b32 offset within row
            uint32_t afr[4][4], bfr[4][2];
#pragma unroll
            for (int i = 0; i < 4; i++) {
                int m0 = wm * 64 + i * 16;
                afr[i][0] = As[(m0 + g)     * APITCH + kb + tg];
                afr[i][1] = As[(m0 + g + 8) * APITCH + kb + tg];
                afr[i][2] = As[(m0 + g)     * APITCH + kb + 4 + tg];
                afr[i][3] = As[(m0 + g + 8) * APITCH + kb + 4 + tg];
            }
#pragma unroll
            for (int j = 0; j < 4; j++) {
                int n0 = wn * 32 + j * 8;
                bfr[j][0] = Bs[(n0 + g) * APITCH + kb + tg];
                bfr[j][1] = Bs[(n0 + g) * APITCH + kb + 4 + tg];
            }
#pragma unroll
            for (int i = 0; i < 4; i++)
#pragma unroll
                for (int j = 0; j < 4; j++) {
                    asm volatile(
                        "mma.sync.aligned.m16n8k16.row.col.f32.bf16.bf16.f32 "
                        "{%0,%1,%2,%3}, {%4,%5,%6,%7}, {%8,%9}, {%0,%1,%2,%3};"
                        : "+f"(acc[i][j][0]), "+f"(acc[i][j][1]), "+f"(acc[i][j][2]), "+f"(acc[i][j][3])
                        : "r"(afr[i][0]), "r"(afr[i][1]), "r"(afr[i][2]), "r"(afr[i][3]),
                          "r"(bfr[j][0]), "r"(bfr[j][1]));
                }
        }
        __syncthreads();
    }

    // ---- epilogue ----
#pragma unroll
    for (int i = 0; i < 4; i++) {
        int r0 = rowBase + wm * 64 + i * 16 + g;
#pragma unroll
        for (int j = 0; j < 4; j++) {
            int c0 = colBase + wn * 32 + j * 8 + tg * 2;
            if (r0 < Nrows) {
                if (c0     < Nout) C[(size_t)r0 * Nout + c0]     = acc[i][j][0];
                if (c0 + 1 < Nout) C[(size_t)r0 * Nout + c0 + 1] = acc[i][j][1];
            }
            if (r0 + 8 < Nrows) {
                if (c0     < Nout) C[(size_t)(r0 + 8) * Nout + c0]     = acc[i][j][2];
                if (c0 + 1 < Nout) C[(size_t)(r0 + 8) * Nout + c0 + 1] = acc[i][j][3];
            }
        }
    }
}

// ---------------- misc kernels (unchanged pipeline) ----------------
__device__ __forceinline__ void atomicMaxF(float* addr, float v) {
    if (v >= 0.f) atomicMax((int*)addr, __float_as_int(v));
    else          atomicMin((unsigned int*)addr, __float_as_uint(v));
}

__global__ void fill_f(float* p, float v, long n) {
    long i = blockIdx.x * (long)blockDim.x + threadIdx.x;
    long stride = (long)gridDim.x * blockDim.x;
    for (; i < n; i += stride) p[i] = v;
}

__global__ void alpha_kernel(const float* __restrict__ xh,
                             const float* __restrict__ asrc,
                             const float* __restrict__ adst,
                             float* __restrict__ as_, float* __restrict__ ad_,
                             int H, int C) {
    int w    = (blockIdx.x * blockDim.x + threadIdx.x) >> 5;
    int lane = threadIdx.x & 31;
    if (w >= NN * H) return;
    int n = w / H, h = w - n * H;
    const float* row = xh + (size_t)n * (H * C) + h * C;
    const float* w1  = asrc + h * C;
    const float* w2  = adst + h * C;
    float s1 = 0.f, s2 = 0.f;
    for (int c = lane; c < C; c += 32) {
        float v = row[c];
        s1 += v * w1[c];
        s2 += v * w2[c];
    }
#pragma unroll
    for (int o = 16; o; o >>= 1) {
        s1 += __shfl_down_sync(0xffffffffu, s1, o);
        s2 += __shfl_down_sync(0xffffffffu, s2, o);
    }
    if (lane == 0) { as_[w] = s1; ad_[w] = s2; }
}

__global__ void edge_max(const int* __restrict__ ei,
                         const float* __restrict__ as_, const float* __restrict__ ad_,
                         float* __restrict__ m_, int H) {
    int i = blockIdx.x * blockDim.x + threadIdx.x;
    if (i >= EE * H) return;
    int e = i / H, h = i - e * H;
    int src = ei[e], dst = ei[EE + e];
    float lg = as_[src * H + h] + ad_[dst * H + h];
    lg = lg > 0.f ? lg : 0.2f * lg;
    atomicMaxF(&m_[dst * H + h], lg);
}

__global__ void edge_sum(const int* __restrict__ ei,
                         const float* __restrict__ as_, const float* __restrict__ ad_,
                         const float* __restrict__ m_, float* __restrict__ den_, int H) {
    int i = blockIdx.x * blockDim.x + threadIdx.x;
    if (i >= EE * H) return;
    int e = i / H, h = i - e * H;
    int src = ei[e], dst = ei[EE + e];
    float lg = as_[src * H + h] + ad_[dst * H + h];
    lg = lg > 0.f ? lg : 0.2f * lg;
    atomicAdd(&den_[dst * H + h], expf(lg - m_[dst * H + h]));
}

__global__ void aggregate(const int* __restrict__ ei,
                          const float* __restrict__ xh,
                          const float* __restrict__ as_, const float* __restrict__ ad_,
                          const float* __restrict__ m_, const float* __restrict__ den_,
                          float* __restrict__ out, int H, int C) {
    int w    = (blockIdx.x * blockDim.x + threadIdx.x) >> 5;
    int lane = threadIdx.x & 31;
    if (w >= EE * H) return;
    int e = w / H, h = w - e * H;
    int src = ei[e], dst = ei[EE + e];
    float lg = as_[src * H + h] + ad_[dst * H + h];
    lg = lg > 0.f ? lg : 0.2f * lg;
    float alpha = expf(lg - m_[dst * H + h]) / (den_[dst * H + h] + 1e-16f);
    const float* xr   = xh  + (size_t)src * (H * C) + h * C;
    float*       orow = out + (size_t)dst * (H * C) + h * C;
    for (int c = lane; c < C; c += 32)
        atomicAdd(&orow[c], alpha * xr[c]);
}

__global__ void final1(const float* __restrict__ agg, const float* __restrict__ b1,
                       const float* __restrict__ lin, const float* __restrict__ lin1b,
                       float* __restrict__ h) {
    long i = blockIdx.x * (long)blockDim.x + threadIdx.x;
    if (i >= (long)NN * M1) return;
    int j = (int)(i % M1);
    float v = agg[i] + b1[j] + lin[i] + lin1b[j];
    h[i] = v > 0.f ? v : expm1f(v);
}

__global__ void final2(const float* __restrict__ agg, const float* __restrict__ b2,
                       float* __restrict__ h) {
    long i = blockIdx.x * (long)blockDim.x + threadIdx.x;
    if (i >= (long)NN * M1) return;
    int j = (int)(i % M1);
    float v = agg[i] + b2[j] + h[i];
    h[i] = v > 0.f ? v : expm1f(v);
}

__global__ void final3(const float* __restrict__ agg, const float* __restrict__ b3,
                       const float* __restrict__ lin, const float* __restrict__ lin3b,
                       float* __restrict__ out) {
    long i = blockIdx.x * (long)blockDim.x + threadIdx.x;
    if (i >= (long)NN * NCLS) return;
    int n = (int)(i / NCLS), k = (int)(i % NCLS);
    const float* ar = agg + (size_t)n * M3;
    float s = 0.25f * (ar[k] + ar[NCLS + k] + ar[2 * NCLS + k] + ar[3 * NCLS + k]);
    out[i] = s + b3[k] + lin[i] + lin3b[k];
}

// ---------------- host orchestration ----------------
static void launch_gemm(const __nv_bfloat16* Ap, const __nv_bfloat16* Bp, float* C,
                        int Nrows, int Kp, int Nout) {
    dim3 gg((Nout + 127) / 128, (Nrows + 127) / 128);
    gemm_mma<<<gg, 256>>>(Ap, Bp, C, Nrows, Kp, Nout);
}

static void edge_softmax_agg(const int* ei, const float* xh, int H, int C,
                             float* agg, float* as_, float* ad_, float* m_, float* den_,
                             const float* asrc, const float* adst) {
    int M = H * C;
    alpha_kernel<<<(NN * H * 32 + 255) / 256, 256>>>(xh, asrc, adst, as_, ad_, H, C);
    fill_f<<<256, 256>>>(m_, -INFINITY, (long)NN * H);
    fill_f<<<256, 256>>>(den_, 0.f, (long)NN * H);
    fill_f<<<4096, 256>>>(agg, 0.f, (long)NN * M);
    edge_max<<<(EE * H + 255) / 256, 256>>>(ei, as_, ad_, m_, H);
    edge_sum<<<(EE * H + 255) / 256, 256>>>(ei, as_, ad_, m_, den_, H);
    aggregate<<<((long)EE * H * 32 + 255) / 256, 256>>>(ei, xh, as_, ad_, m_, den_, agg, H, C);
}

extern "C" void kernel_launch(void* const* d_in, const int* in_sizes, int n_in,
                              void* d_out, int out_size) {
    const float* x      = (const float*)d_in[0];
    const int*   ei     = (const int*)  d_in[1];
    const float* W1     = (const float*)d_in[2];
    const float* a1s    = (const float*)d_in[3];
    const float* a1d    = (const float*)d_in[4];
    const float* b1     = (const float*)d_in[5];
    const float* lin1W  = (const float*)d_in[6];
    const float* lin1b  = (const float*)d_in[7];
    const float* W2     = (const float*)d_in[8];
    const float* a2s    = (const float*)d_in[9];
    const float* a2d    = (const float*)d_in[10];
    const float* b2     = (const float*)d_in[11];
    const float* W3     = (const float*)d_in[12];
    const float* a3s    = (const float*)d_in[13];
    const float* a3d    = (const float*)d_in[14];
    const float* b3     = (const float*)d_in[15];
    const float* lin3W  = (const float*)d_in[16];
    const float* lin3b  = (const float*)d_in[17];
    float* out = (float*)d_out;

    float *xh, *agg, *lin, *h, *as_, *ad_, *m_, *den_;
    __nv_bfloat16 *Ah, *Bt;
    cudaGetSymbolAddress((void**)&xh,  g_xh);
    cudaGetSymbolAddress((void**)&agg, g_agg);
    cudaGetSymbolAddress((void**)&lin, g_lin);
    cudaGetSymbolAddress((void**)&h,   g_h);
    cudaGetSymbolAddress((void**)&as_, g_as);
    cudaGetSymbolAddress((void**)&ad_, g_ad);
    cudaGetSymbolAddress((void**)&m_,  g_m);
    cudaGetSymbolAddress((void**)&den_, g_den);
    cudaGetSymbolAddress((void**)&Ah,  g_Ah);
    cudaGetSymbolAddress((void**)&Bt,  g_Bt);

    // ---- layer 1: h1 = elu(GAT1(x) + b1 + x@lin1_W + lin1_b) ----
    convA<<<2048, 256>>>(x, Ah, NN, FIN);                   // K'=384
    convB<<<(256 * FIN + 255) / 256, 256>>>(W1, Bt, FIN, M1, 256);
    launch_gemm(Ah, Bt, xh, NN, 3 * FIN, M1);
    edge_softmax_agg(ei, xh, HEADS, HID, agg, as_, ad_, m_, den_, a1s, a1d);
    convB<<<(256 * FIN + 255) / 256, 256>>>(lin1W, Bt, FIN, M1, 256);
    launch_gemm(Ah, Bt, lin, NN, 3 * FIN, M1);
    final1<<<((long)NN * M1 + 255) / 256, 256>>>(agg, b1, lin, lin1b, h);

    // ---- layer 2: h2 = elu(GAT2(h1) + b2 + h1) ----
    convA<<<4096, 256>>>(h, Ah, NN, M1);                    // K'=768
    convB<<<(256 * M1 + 255) / 256, 256>>>(W2, Bt, M1, M1, 256);
    launch_gemm(Ah, Bt, xh, NN, 3 * M1, M1);
    edge_softmax_agg(ei, xh, HEADS, HID, agg, as_, ad_, m_, den_, a2s, a2d);
    final2<<<((long)NN * M1 + 255) / 256, 256>>>(agg, b2, h);

    // ---- layer 3: out = mean_heads(GAT3(h2)) + b3 + h2@lin3_W + lin3_b ----
    convA<<<4096, 256>>>(h, Ah, NN, M1);
    convB<<<(512 * M1 + 255) / 256, 256>>>(W3, Bt, M1, M3, 512);
    launch_gemm(Ah, Bt, xh, NN, 3 * M1, M3);
    edge_softmax_agg(ei, xh, HEADS, NCLS, agg, as_, ad_, m_, den_, a3s, a3d);
    convB<<<(128 * M1 + 255) / 256, 256>>>(lin3W, Bt, M1, NCLS, 128);
    launch_gemm(Ah, Bt, lin, NN, 3 * M1, NCLS);
    final3<<<((long)NN * NCLS + 255) / 256, 256>>>(agg, b3, lin, lin3b, out);

    (void)in_sizes; (void)n_in; (void)out_size;
}

// round 5
// speedup vs baseline: 1.3341x; 1.3282x over previous
#include <cuda_runtime.h>
#include <cuda_bf16.h>
#include <math.h>
#include <stdint.h>

#define NN   50000
#define EE   400000
#define FIN  128
#define HID  64
#define HEADS 4
#define NCLS 121
#define M1   256   // HEADS*HID
#define M3   484   // OUT_HEADS*NCLS

// ---------------- scratch (static device globals; no allocation) ----------------
__device__ float g_xh [(size_t)NN * M3];   // transformed features [N, M]
__device__ float g_agg[(size_t)NN * M3];   // aggregation output   [N, M]
__device__ float g_lin[(size_t)NN * M1];   // linear-skip outputs
__device__ float g_h  [(size_t)NN * M1];   // hidden features h1 / h2
__device__ float g_as [NN * HEADS];
__device__ float g_ad [NN * HEADS];
__device__ __nv_bfloat16 g_Ah[(size_t)50048 * 768]; // A' = [Xh | Xh | Xl], padded rows
__device__ __nv_bfloat16 g_Bt[(size_t)512 * 768];   // B' transposed = [Wh | Wl | Wh]
// CSR (built per launch from edge_index)
__device__ int   g_deg   [NN];
__device__ int   g_rowptr[NN + 1];
__device__ int   g_cursor[NN];
__device__ int   g_csrsrc[EE];
__device__ float g_alpha [(size_t)EE * HEADS];

// ---------------- bf16 hi/lo conversion kernels ----------------
__global__ void convA(const float* __restrict__ X, __nv_bfloat16* __restrict__ Ap, int Nrows, int K) {
    long i = blockIdx.x * (long)blockDim.x + threadIdx.x;
    long tot = (long)Nrows * K;
    long stride = (long)gridDim.x * blockDim.x;
    for (; i < tot; i += stride) {
        int r = (int)(i / K), k = (int)(i - (long)r * K);
        float x = X[i];
        __nv_bfloat16 h = __float2bfloat16(x);
        __nv_bfloat16 l = __float2bfloat16(x - __bfloat162float(h));
        __nv_bfloat16* row = Ap + (size_t)r * (3 * K);
        row[k] = h; row[K + k] = h; row[2 * K + k] = l;
    }
}
__global__ void convB(const float* __restrict__ W, __nv_bfloat16* __restrict__ Bp, int K, int M, int Npad) {
    long i = blockIdx.x * (long)blockDim.x + threadIdx.x;
    long tot = (long)Npad * K;
    if (i >= tot) return;
    int n = (int)(i / K), k = (int)(i - (long)n * K);
    float w = (n < M) ? W[(size_t)k * M + n] : 0.f;
    __nv_bfloat16 h = __float2bfloat16(w);
    __nv_bfloat16 l = __float2bfloat16(w - __bfloat162float(h));
    __nv_bfloat16* row = Bp + (size_t)n * (3 * K);
    row[k] = h; row[K + k] = l; row[2 * K + k] = h;
}

// ---------------- HMMA GEMM (unchanged from R3, passing) ----------------
#define APITCH 17
__global__ __launch_bounds__(256) void gemm_mma(const __nv_bfloat16* __restrict__ A,
                                                const __nv_bfloat16* __restrict__ Bt,
                                                float* __restrict__ C,
                                                int Nrows, int Kp, int Nout) {
    __shared__ uint32_t As[128 * APITCH];
    __shared__ uint32_t Bs[128 * APITCH];
    int tid  = threadIdx.x;
    int wid  = tid >> 5, lane = tid & 31;
    int wm   = wid & 1;
    int wn   = wid >> 1;
    int g    = lane >> 2;
    int tg   = lane & 3;
    int rowBase = blockIdx.y * 128;
    int colBase = blockIdx.x * 128;

    float acc[4][4][4];
#pragma unroll
    for (int i = 0; i < 4; i++)
#pragma unroll
        for (int j = 0; j < 4; j++)
#pragma unroll
            for (int q = 0; q < 4; q++) acc[i][j][q] = 0.f;

    int lr   = tid >> 1;
    int half = tid & 1;

    for (int k0 = 0; k0 < Kp; k0 += 32) {
        {
            int grow = rowBase + lr;
            uint4 v0 = make_uint4(0, 0, 0, 0), v1 = v0;
            if (grow < Nrows) {
                const uint4* p = (const uint4*)(A + (size_t)grow * Kp + k0 + half * 16);
                v0 = p[0]; v1 = p[1];
            }
            uint32_t* d = As + lr * APITCH + half * 8;
            d[0] = v0.x; d[1] = v0.y; d[2] = v0.z; d[3] = v0.w;
            d[4] = v1.x; d[5] = v1.y; d[6] = v1.z; d[7] = v1.w;
        }
        {
            const uint4* p = (const uint4*)(Bt + (size_t)(colBase + lr) * Kp + k0 + half * 16);
            uint4 v0 = p[0], v1 = p[1];
            uint32_t* d = Bs + lr * APITCH + half * 8;
            d[0] = v0.x; d[1] = v0.y; d[2] = v0.z; d[3] = v0.w;
            d[4] = v1.x; d[5] = v1.y; d[6] = v1.z; d[7] = v1.w;
        }
        __syncthreads();

#pragma unroll
        for (int ks = 0; ks < 2; ks++) {
            int kb = ks * 8;
            uint32_t afr[4][4], bfr[4][2];
#pragma unroll
            for (int i = 0; i < 4; i++) {
                int m0 = wm * 64 + i * 16;
                afr[i][0] = As[(m0 + g)     * APITCH + kb + tg];
                afr[i][1] = As[(m0 + g + 8) * APITCH + kb + tg];
                afr[i][2] = As[(m0 + g)     * APITCH + kb + 4 + tg];
                afr[i][3] = As[(m0 + g + 8) * APITCH + kb + 4 + tg];
            }
#pragma unroll
            for (int j = 0; j < 4; j++) {
                int n0 = wn * 32 + j * 8;
                bfr[j][0] = Bs[(n0 + g) * APITCH + kb + tg];
                bfr[j][1] = Bs[(n0 + g) * APITCH + kb + 4 + tg];
            }
#pragma unroll
            for (int i = 0; i < 4; i++)
#pragma unroll
                for (int j = 0; j < 4; j++) {
                    asm volatile(
                        "mma.sync.aligned.m16n8k16.row.col.f32.bf16.bf16.f32 "
                        "{%0,%1,%2,%3}, {%4,%5,%6,%7}, {%8,%9}, {%0,%1,%2,%3};"
                        : "+f"(acc[i][j][0]), "+f"(acc[i][j][1]), "+f"(acc[i][j][2]), "+f"(acc[i][j][3])
                        : "r"(afr[i][0]), "r"(afr[i][1]), "r"(afr[i][2]), "r"(afr[i][3]),
                          "r"(bfr[j][0]), "r"(bfr[j][1]));
                }
        }
        __syncthreads();
    }

#pragma unroll
    for (int i = 0; i < 4; i++) {
        int r0 = rowBase + wm * 64 + i * 16 + g;
#pragma unroll
        for (int j = 0; j < 4; j++) {
            int c0 = colBase + wn * 32 + j * 8 + tg * 2;
            if (r0 < Nrows) {
                if (c0     < Nout) C[(size_t)r0 * Nout + c0]     = acc[i][j][0];
                if (c0 + 1 < Nout) C[(size_t)r0 * Nout + c0 + 1] = acc[i][j][1];
            }
            if (r0 + 8 < Nrows) {
                if (c0     < Nout) C[(size_t)(r0 + 8) * Nout + c0]     = acc[i][j][2];
                if (c0 + 1 < Nout) C[(size_t)(r0 + 8) * Nout + c0 + 1] = acc[i][j][3];
            }
        }
    }
}

// ---------------- CSR construction ----------------
__global__ void zero_i(int* p, int n) {
    int i = blockIdx.x * blockDim.x + threadIdx.x;
    if (i < n) p[i] = 0;
}
__global__ void hist_dst(const int* __restrict__ ei, int* __restrict__ deg) {
    int e = blockIdx.x * blockDim.x + threadIdx.x;
    if (e < EE) atomicAdd(&deg[ei[EE + e]], 1);
}
// single block, 512 threads: chunked exclusive scan of deg -> rowptr, cursor
__global__ void scan_deg(const int* __restrict__ deg, int* __restrict__ rowptr, int* __restrict__ cursor) {
    __shared__ int part[512];
    int t = threadIdx.x;
    const int CH = (NN + 511) / 512;
    int start = t * CH;
    int s = 0;
    for (int i = 0; i < CH; i++) {
        int idx = start + i;
        if (idx < NN) s += deg[idx];
    }
    part[t] = s;
    __syncthreads();
    for (int off = 1; off < 512; off <<= 1) {
        int v = (t >= off) ? part[t - off] : 0;
        __syncthreads();
        part[t] += v;
        __syncthreads();
    }
    int base = (t == 0) ? 0 : part[t - 1];
    for (int i = 0; i < CH; i++) {
        int idx = start + i;
        if (idx < NN) {
            rowptr[idx] = base;
            cursor[idx] = base;
            base += deg[idx];
        }
    }
    if (t == 511) rowptr[NN] = part[511];
}
__global__ void scatter_csr(const int* __restrict__ ei, int* __restrict__ cursor,
                            int* __restrict__ csrsrc) {
    int e = blockIdx.x * blockDim.x + threadIdx.x;
    if (e >= EE) return;
    int dst = ei[EE + e];
    int p = atomicAdd(&cursor[dst], 1);
    csrsrc[p] = ei[e];
}

// ---------------- alpha_s / alpha_d: warp per (node, head) ----------------
__global__ void alpha_kernel(const float* __restrict__ xh,
                             const float* __restrict__ asrc,
                             const float* __restrict__ adst,
                             float* __restrict__ as_, float* __restrict__ ad_,
                             int H, int C) {
    int w    = (blockIdx.x * blockDim.x + threadIdx.x) >> 5;
    int lane = threadIdx.x & 31;
    if (w >= NN * H) return;
    int n = w / H, h = w - n * H;
    const float* row = xh + (size_t)n * (H * C) + h * C;
    const float* w1  = asrc + h * C;
    const float* w2  = adst + h * C;
    float s1 = 0.f, s2 = 0.f;
    for (int c = lane; c < C; c += 32) {
        float v = row[c];
        s1 += v * w1[c];
        s2 += v * w2[c];
    }
#pragma unroll
    for (int o = 16; o; o >>= 1) {
        s1 += __shfl_down_sync(0xffffffffu, s1, o);
        s2 += __shfl_down_sync(0xffffffffu, s2, o);
    }
    if (lane == 0) { as_[w] = s1; ad_[w] = s2; }
}

// ---------------- per-node edge softmax over CSR: warp per node ----------------
__global__ void softmax_csr(const int* __restrict__ rowptr, const int* __restrict__ csrsrc,
                            const float* __restrict__ as_, const float* __restrict__ ad_,
                            float* __restrict__ alpha) {
    int w    = (blockIdx.x * blockDim.x + threadIdx.x) >> 5;
    int lane = threadIdx.x & 31;
    if (w >= NN) return;
    int h  = lane >> 3;   // 4 heads x 8 edge slots
    int j0 = lane & 7;
    int beg = rowptr[w], end = rowptr[w + 1];
    float adv = ad_[w * HEADS + h];
    float m = -INFINITY;
    for (int i = beg + j0; i < end; i += 8) {
        float lg = as_[csrsrc[i] * HEADS + h] + adv;
        lg = lg > 0.f ? lg : 0.2f * lg;
        m = fmaxf(m, lg);
    }
#pragma unroll
    for (int o = 1; o < 8; o <<= 1) m = fmaxf(m, __shfl_xor_sync(0xffffffffu, m, o));
    float den = 0.f;
    for (int i = beg + j0; i < end; i += 8) {
        float lg = as_[csrsrc[i] * HEADS + h] + adv;
        lg = lg > 0.f ? lg : 0.2f * lg;
        den += expf(lg - m);
    }
#pragma unroll
    for (int o = 1; o < 8; o <<= 1) den += __shfl_xor_sync(0xffffffffu, den, o);
    float inv = 1.f / (den + 1e-16f);
    for (int i = beg + j0; i < end; i += 8) {
        float lg = as_[csrsrc[i] * HEADS + h] + adv;
        lg = lg > 0.f ? lg : 0.2f * lg;
        alpha[(size_t)i * HEADS + h] = expf(lg - m) * inv;
    }
}

// ---------------- aggregation over CSR: block per node, thread per channel ----------------
__global__ void agg_csr(const int* __restrict__ rowptr, const int* __restrict__ csrsrc,
                        const float* __restrict__ alpha, const float* __restrict__ xh,
                        float* __restrict__ out, int M, int Cper) {
    int n = blockIdx.x;
    int c = threadIdx.x;
    if (c >= M) return;
    int h = c / Cper;
    int beg = rowptr[n], end = rowptr[n + 1];
    float acc = 0.f;
    for (int i = beg; i < end; i++) {
        float a = alpha[(size_t)i * HEADS + h];
        acc += a * xh[(size_t)csrsrc[i] * M + c];
    }
    out[(size_t)n * M + c] = acc;
}

// ---------------- finalize kernels ----------------
__global__ void final1(const float* __restrict__ agg, const float* __restrict__ b1,
                       const float* __restrict__ lin, const float* __restrict__ lin1b,
                       float* __restrict__ h) {
    long i = blockIdx.x * (long)blockDim.x + threadIdx.x;
    if (i >= (long)NN * M1) return;
    int j = (int)(i % M1);
    float v = agg[i] + b1[j] + lin[i] + lin1b[j];
    h[i] = v > 0.f ? v : expm1f(v);
}
__global__ void final2(const float* __restrict__ agg, const float* __restrict__ b2,
                       float* __restrict__ h) {
    long i = blockIdx.x * (long)blockDim.x + threadIdx.x;
    if (i >= (long)NN * M1) return;
    int j = (int)(i % M1);
    float v = agg[i] + b2[j] + h[i];
    h[i] = v > 0.f ? v : expm1f(v);
}
__global__ void final3(const float* __restrict__ agg, const float* __restrict__ b3,
                       const float* __restrict__ lin, const float* __restrict__ lin3b,
                       float* __restrict__ out) {
    long i = blockIdx.x * (long)blockDim.x + threadIdx.x;
    if (i >= (long)NN * NCLS) return;
    int n = (int)(i / NCLS), k = (int)(i % NCLS);
    const float* ar = agg + (size_t)n * M3;
    float s = 0.25f * (ar[k] + ar[NCLS + k] + ar[2 * NCLS + k] + ar[3 * NCLS + k]);
    out[i] = s + b3[k] + lin[i] + lin3b[k];
}

// ---------------- host orchestration ----------------
static void launch_gemm(const __nv_bfloat16* Ap, const __nv_bfloat16* Bp, float* C,
                        int Nrows, int Kp, int Nout) {
    dim3 gg((Nout + 127) / 128, (Nrows + 127) / 128);
    gemm_mma<<<gg, 256>>>(Ap, Bp, C, Nrows, Kp, Nout);
}

static void edge_softmax_agg(const int* rowptr, const int* csrsrc, const float* xh,
                             int H, int C, float* agg, float* as_, float* ad_, float* alpha,
                             const float* asrc, const float* adst) {
    int M = H * C;
    alpha_kernel<<<(NN * H * 32 + 255) / 256, 256>>>(xh, asrc, adst, as_, ad_, H, C);
    softmax_csr<<<(NN * 32 + 255) / 256, 256>>>(rowptr, csrsrc, as_, ad_, alpha);
    int bdim = (M + 31) & ~31;
    agg_csr<<<NN, bdim>>>(rowptr, csrsrc, alpha, xh, agg, M, C);
}

extern "C" void kernel_launch(void* const* d_in, const int* in_sizes, int n_in,
                              void* d_out, int out_size) {
    const float* x      = (const float*)d_in[0];
    const int*   ei     = (const int*)  d_in[1];
    const float* W1     = (const float*)d_in[2];
    const float* a1s    = (const float*)d_in[3];
    const float* a1d    = (const float*)d_in[4];
    const float* b1     = (const float*)d_in[5];
    const float* lin1W  = (const float*)d_in[6];
    const float* lin1b  = (const float*)d_in[7];
    const float* W2     = (const float*)d_in[8];
    const float* a2s    = (const float*)d_in[9];
    const float* a2d    = (const float*)d_in[10];
    const float* b2     = (const float*)d_in[11];
    const float* W3     = (const float*)d_in[12];
    const float* a3s    = (const float*)d_in[13];
    const float* a3d    = (const float*)d_in[14];
    const float* b3     = (const float*)d_in[15];
    const float* lin3W  = (const float*)d_in[16];
    const float* lin3b  = (const float*)d_in[17];
    float* out = (float*)d_out;

    float *xh, *agg, *lin, *h, *as_, *ad_, *alpha;
    __nv_bfloat16 *Ah, *Bt;
    int *deg, *rowptr, *cursor, *csrsrc;
    cudaGetSymbolAddress((void**)&xh,  g_xh);
    cudaGetSymbolAddress((void**)&agg, g_agg);
    cudaGetSymbolAddress((void**)&lin, g_lin);
    cudaGetSymbolAddress((void**)&h,   g_h);
    cudaGetSymbolAddress((void**)&as_, g_as);
    cudaGetSymbolAddress((void**)&ad_, g_ad);
    cudaGetSymbolAddress((void**)&alpha, g_alpha);
    cudaGetSymbolAddress((void**)&Ah,  g_Ah);
    cudaGetSymbolAddress((void**)&Bt,  g_Bt);
    cudaGetSymbolAddress((void**)&deg,    g_deg);
    cudaGetSymbolAddress((void**)&rowptr, g_rowptr);
    cudaGetSymbolAddress((void**)&cursor, g_cursor);
    cudaGetSymbolAddress((void**)&csrsrc, g_csrsrc);

    // ---- CSR build (edge_index is shared across layers) ----
    zero_i<<<(NN + 255) / 256, 256>>>(deg, NN);
    hist_dst<<<(EE + 255) / 256, 256>>>(ei, deg);
    scan_deg<<<1, 512>>>(deg, rowptr, cursor);
    scatter_csr<<<(EE + 255) / 256, 256>>>(ei, cursor, csrsrc);

    // ---- layer 1: h1 = elu(GAT1(x) + b1 + x@lin1_W + lin1_b) ----
    convA<<<2048, 256>>>(x, Ah, NN, FIN);
    convB<<<(256 * FIN + 255) / 256, 256>>>(W1, Bt, FIN, M1, 256);
    launch_gemm(Ah, Bt, xh, NN, 3 * FIN, M1);
    edge_softmax_agg(rowptr, csrsrc, xh, HEADS, HID, agg, as_, ad_, alpha, a1s, a1d);
    convB<<<(256 * FIN + 255) / 256, 256>>>(lin1W, Bt, FIN, M1, 256);
    launch_gemm(Ah, Bt, lin, NN, 3 * FIN, M1);
    final1<<<((long)NN * M1 + 255) / 256, 256>>>(agg, b1, lin, lin1b, h);

    // ---- layer 2: h2 = elu(GAT2(h1) + b2 + h1) ----
    convA<<<4096, 256>>>(h, Ah, NN, M1);
    convB<<<(256 * M1 + 255) / 256, 256>>>(W2, Bt, M1, M1, 256);
    launch_gemm(Ah, Bt, xh, NN, 3 * M1, M1);
    edge_softmax_agg(rowptr, csrsrc, xh, HEADS, HID, agg, as_, ad_, alpha, a2s, a2d);
    final2<<<((long)NN * M1 + 255) / 256, 256>>>(agg, b2, h);

    // ---- layer 3: out = mean_heads(GAT3(h2)) + b3 + h2@lin3_W + lin3_b ----
    convA<<<4096, 256>>>(h, Ah, NN, M1);
    convB<<<(512 * M1 + 255) / 256, 256>>>(W3, Bt, M1, M3, 512);
    launch_gemm(Ah, Bt, xh, NN, 3 * M1, M3);
    edge_softmax_agg(rowptr, csrsrc, xh, HEADS, NCLS, agg, as_, ad_, alpha, a3s, a3d);
    convB<<<(128 * M1 + 255) / 256, 256>>>(lin3W, Bt, M1, NCLS, 128);
    launch_gemm(Ah, Bt, lin, NN, 3 * M1, NCLS);
    final3<<<((long)NN * NCLS + 255) / 256, 256>>>(agg, b3, lin, lin3b, out);

    (void)in_sizes; (void)n_in; (void)out_size;
}

// round 6
// speedup vs baseline: 1.4689x; 1.1010x over previous
#include <cuda_runtime.h>
#include <cuda_bf16.h>
#include <math.h>
#include <stdint.h>

#define NN   50000
#define EE   400000
#define FIN  128
#define HID  64
#define HEADS 4
#define NCLS 121
#define M1   256   // HEADS*HID
#define M3   484   // OUT_HEADS*NCLS
#define NPAD 50048 // 391 * 128

// ---------------- scratch (static device globals; no allocation) ----------------
__device__ float g_xh [(size_t)NN * M3];   // transformed features [N, M]
__device__ float g_agg[(size_t)NN * M3];   // aggregation output   [N, M]
__device__ float g_lin[(size_t)NN * M1];   // linear-skip outputs
__device__ float g_h  [(size_t)NN * M1];   // hidden features h1 / h2
__device__ float g_as [NN * HEADS];
__device__ float g_ad [NN * HEADS];
__device__ __nv_bfloat16 g_Ah[(size_t)NPAD * 768]; // A' = [Xh | Xh | Xl], padded rows
__device__ __nv_bfloat16 g_Bt[(size_t)512 * 768];  // B' transposed = [Wh | Wl | Wh]
// CSR
__device__ int   g_deg   [NN];
__device__ int   g_rowptr[NN + 1];
__device__ int   g_cursor[NN];
__device__ int   g_csrsrc[EE];
__device__ float g_alpha [(size_t)EE * HEADS];

// ---------------- conversion (layer-1 input only; layers 2/3 fused into finals) ----
__global__ void convA(const float* __restrict__ X, __nv_bfloat16* __restrict__ Ap, int Nrows, int K) {
    long i = blockIdx.x * (long)blockDim.x + threadIdx.x;
    long tot = (long)Nrows * K;
    long stride = (long)gridDim.x * blockDim.x;
    for (; i < tot; i += stride) {
        int r = (int)(i / K), k = (int)(i - (long)r * K);
        float x = X[i];
        __nv_bfloat16 h = __float2bfloat16(x);
        __nv_bfloat16 l = __float2bfloat16(x - __bfloat162float(h));
        __nv_bfloat16* row = Ap + (size_t)r * (3 * K);
        row[k] = h; row[K + k] = h; row[2 * K + k] = l;
    }
}
__global__ void convB(const float* __restrict__ W, __nv_bfloat16* __restrict__ Bp, int K, int M, int Npad) {
    long i = blockIdx.x * (long)blockDim.x + threadIdx.x;
    long tot = (long)Npad * K;
    if (i >= tot) return;
    int n = (int)(i / K), k = (int)(i - (long)n * K);
    float w = (n < M) ? W[(size_t)k * M + n] : 0.f;
    __nv_bfloat16 h = __float2bfloat16(w);
    __nv_bfloat16 l = __float2bfloat16(w - __bfloat162float(h));
    __nv_bfloat16* row = Bp + (size_t)n * (3 * K);
    row[k] = h; row[K + k] = l; row[2 * K + k] = h;
}

// ---------------- pipelined HMMA GEMM ----------------
// C[Nrows x Nout] = A[NPAD x Kp] . Bt[Npad x Kp]^T, tile 128x128x32, 8 warps (64x32 each),
// cp.async double buffer + ldmatrix.x4, 80B smem row pitch (conflict-free).
#define PITCH 80
#define STAGE_BYTES (128 * PITCH)            // 10240 per tile
__global__ __launch_bounds__(256) void gemm_mma(const __nv_bfloat16* __restrict__ A,
                                                const __nv_bfloat16* __restrict__ Bt,
                                                float* __restrict__ C,
                                                int Nrows, int Kp, int Nout) {
    __shared__ __align__(16) uint8_t smem[4 * STAGE_BYTES];  // A0,B0,A1,B1
    uint32_t sbase = (uint32_t)__cvta_generic_to_shared(smem);

    int tid  = threadIdx.x;
    int wid  = tid >> 5, lane = tid & 31;
    int wm   = wid & 1;          // 64-row slab
    int wn   = wid >> 1;         // 32-col slab
    int g    = lane >> 2;        // 0..7
    int tg   = lane & 3;         // 0..3
    int rowBase = blockIdx.y * 128;
    int colBase = blockIdx.x * 128;

    // per-lane ldmatrix address components: mat = lane>>3, r = lane&7
    int lrow = (lane & 7) + ((lane >> 3) & 1) * 8;   // row within 16-row group
    int lcol = (lane >> 4) * 16;                     // byte offset for k-half

    float acc[4][4][4];
#pragma unroll
    for (int i = 0; i < 4; i++)
#pragma unroll
        for (int j = 0; j < 4; j++)
#pragma unroll
            for (int q = 0; q < 4; q++) acc[i][j][q] = 0.f;

    int isB = tid >> 7;          // 0: load A rows, 1: load B rows
    int lr  = tid & 127;
    const __nv_bfloat16* gsrc = isB ? (Bt + (size_t)(colBase + lr) * Kp)
                                    : (A  + (size_t)(rowBase + lr) * Kp);
    int niter = Kp >> 5;

    // ---- prologue: stage 0 ----
    {
        uint32_t dst = sbase + (uint32_t)isB * STAGE_BYTES + lr * PITCH;
        const uint8_t* src = (const uint8_t*)(gsrc);
#pragma unroll
        for (int c = 0; c < 4; c++) {
            asm volatile("cp.async.cg.shared.global [%0], [%1], 16;"
                         :: "r"(dst + c * 16), "l"(src + c * 16) : "memory");
        }
        asm volatile("cp.async.commit_group;" ::: "memory");
    }

    for (int it = 0; it < niter; it++) {
        if (it + 1 < niter) {
            uint32_t dst = sbase + ((it + 1) & 1) * 2 * STAGE_BYTES + (uint32_t)isB * STAGE_BYTES + lr * PITCH;
            const uint8_t* src = (const uint8_t*)(gsrc + (it + 1) * 32);
#pragma unroll
            for (int c = 0; c < 4; c++) {
                asm volatile("cp.async.cg.shared.global [%0], [%1], 16;"
                             :: "r"(dst + c * 16), "l"(src + c * 16) : "memory");
            }
            asm volatile("cp.async.commit_group;" ::: "memory");
            asm volatile("cp.async.wait_group 1;" ::: "memory");
        } else {
            asm volatile("cp.async.wait_group 0;" ::: "memory");
        }
        __syncthreads();

        uint32_t sA = sbase + (it & 1) * 2 * STAGE_BYTES;
        uint32_t sB = sA + STAGE_BYTES;

#pragma unroll
        for (int ks = 0; ks < 2; ks++) {
            int kbyte = ks * 32;
            uint32_t a[4][4], b[2][4];
#pragma unroll
            for (int i = 0; i < 4; i++) {
                uint32_t addr = sA + (wm * 64 + i * 16 + lrow) * PITCH + kbyte + lcol;
                asm volatile("ldmatrix.sync.aligned.m8n8.x4.shared.b16 {%0,%1,%2,%3}, [%4];"
                             : "=r"(a[i][0]), "=r"(a[i][1]), "=r"(a[i][2]), "=r"(a[i][3]) : "r"(addr));
            }
#pragma unroll
            for (int p = 0; p < 2; p++) {
                uint32_t addr = sB + (wn * 32 + p * 16 + lrow) * PITCH + kbyte + lcol;
                asm volatile("ldmatrix.sync.aligned.m8n8.x4.shared.b16 {%0,%1,%2,%3}, [%4];"
                             : "=r"(b[p][0]), "=r"(b[p][1]), "=r"(b[p][2]), "=r"(b[p][3]) : "r"(addr));
            }
#pragma unroll
            for (int i = 0; i < 4; i++) {
#pragma unroll
                for (int j = 0; j < 4; j++) {
                    uint32_t b0 = b[j >> 1][j & 1];        // tile j regs: (b[p][0|1], b[p][2|3])
                    uint32_t b1 = b[j >> 1][2 + (j & 1)];
                    asm volatile(
                        "mma.sync.aligned.m16n8k16.row.col.f32.bf16.bf16.f32 "
                        "{%0,%1,%2,%3}, {%4,%5,%6,%7}, {%8,%9}, {%0,%1,%2,%3};"
                        : "+f"(acc[i][j][0]), "+f"(acc[i][j][1]), "+f"(acc[i][j][2]), "+f"(acc[i][j][3])
                        : "r"(a[i][0]), "r"(a[i][1]), "r"(a[i][2]), "r"(a[i][3]),
                          "r"(b0), "r"(b1));
                }
            }
        }
        __syncthreads();
    }

    // ---- epilogue ----
#pragma unroll
    for (int i = 0; i < 4; i++) {
        int r0 = rowBase + wm * 64 + i * 16 + g;
#pragma unroll
        for (int j = 0; j < 4; j++) {
            int c0 = colBase + wn * 32 + j * 8 + tg * 2;
            if (r0 < Nrows) {
                if (c0     < Nout) C[(size_t)r0 * Nout + c0]     = acc[i][j][0];
                if (c0 + 1 < Nout) C[(size_t)r0 * Nout + c0 + 1] = acc[i][j][1];
            }
            if (r0 + 8 < Nrows) {
                if (c0     < Nout) C[(size_t)(r0 + 8) * Nout + c0]     = acc[i][j][2];
                if (c0 + 1 < Nout) C[(size_t)(r0 + 8) * Nout + c0 + 1] = acc[i][j][3];
            }
        }
    }
}

// ---------------- CSR construction ----------------
__global__ void zero_i(int* p, int n) {
    int i = blockIdx.x * blockDim.x + threadIdx.x;
    if (i < n) p[i] = 0;
}
__global__ void hist_dst(const int* __restrict__ ei, int* __restrict__ deg) {
    int e = blockIdx.x * blockDim.x + threadIdx.x;
    if (e < EE) atomicAdd(&deg[ei[EE + e]], 1);
}
__global__ void scan_deg(const int* __restrict__ deg, int* __restrict__ rowptr, int* __restrict__ cursor) {
    __shared__ int part[512];
    int t = threadIdx.x;
    const int CH = (NN + 511) / 512;
    int start = t * CH;
    int s = 0;
    for (int i = 0; i < CH; i++) {
        int idx = start + i;
        if (idx < NN) s += deg[idx];
    }
    part[t] = s;
    __syncthreads();
    for (int off = 1; off < 512; off <<= 1) {
        int v = (t >= off) ? part[t - off] : 0;
        __syncthreads();
        part[t] += v;
        __syncthreads();
    }
    int base = (t == 0) ? 0 : part[t - 1];
    for (int i = 0; i < CH; i++) {
        int idx = start + i;
        if (idx < NN) {
            rowptr[idx] = base;
            cursor[idx] = base;
            base += deg[idx];
        }
    }
    if (t == 511) rowptr[NN] = part[511];
}
__global__ void scatter_csr(const int* __restrict__ ei, int* __restrict__ cursor,
                            int* __restrict__ csrsrc) {
    int e = blockIdx.x * blockDim.x + threadIdx.x;
    if (e >= EE) return;
    int dst = ei[EE + e];
    int p = atomicAdd(&cursor[dst], 1);
    csrsrc[p] = ei[e];
}

// ---------------- alpha_s / alpha_d ----------------
__global__ void alpha_kernel(const float* __restrict__ xh,
                             const float* __restrict__ asrc,
                             const float* __restrict__ adst,
                             float* __restrict__ as_, float* __restrict__ ad_,
                             int H, int C) {
    int w    = (blockIdx.x * blockDim.x + threadIdx.x) >> 5;
    int lane = threadIdx.x & 31;
    if (w >= NN * H) return;
    int n = w / H, h = w - n * H;
    const float* row = xh + (size_t)n * (H * C) + h * C;
    const float* w1  = asrc + h * C;
    const float* w2  = adst + h * C;
    float s1 = 0.f, s2 = 0.f;
    for (int c = lane; c < C; c += 32) {
        float v = row[c];
        s1 += v * w1[c];
        s2 += v * w2[c];
    }
#pragma unroll
    for (int o = 16; o; o >>= 1) {
        s1 += __shfl_down_sync(0xffffffffu, s1, o);
        s2 += __shfl_down_sync(0xffffffffu, s2, o);
    }
    if (lane == 0) { as_[w] = s1; ad_[w] = s2; }
}

// ---------------- per-node edge softmax ----------------
__global__ void softmax_csr(const int* __restrict__ rowptr, const int* __restrict__ csrsrc,
                            const float* __restrict__ as_, const float* __restrict__ ad_,
                            float* __restrict__ alpha) {
    int w    = (blockIdx.x * blockDim.x + threadIdx.x) >> 5;
    int lane = threadIdx.x & 31;
    if (w >= NN) return;
    int h  = lane >> 3;
    int j0 = lane & 7;
    int beg = rowptr[w], end = rowptr[w + 1];
    float adv = ad_[w * HEADS + h];
    float m = -INFINITY;
    for (int i = beg + j0; i < end; i += 8) {
        float lg = as_[csrsrc[i] * HEADS + h] + adv;
        lg = lg > 0.f ? lg : 0.2f * lg;
        m = fmaxf(m, lg);
    }
#pragma unroll
    for (int o = 1; o < 8; o <<= 1) m = fmaxf(m, __shfl_xor_sync(0xffffffffu, m, o));
    float den = 0.f;
    for (int i = beg + j0; i < end; i += 8) {
        float lg = as_[csrsrc[i] * HEADS + h] + adv;
        lg = lg > 0.f ? lg : 0.2f * lg;
        den += expf(lg - m);
    }
#pragma unroll
    for (int o = 1; o < 8; o <<= 1) den += __shfl_xor_sync(0xffffffffu, den, o);
    float inv = 1.f / (den + 1e-16f);
    for (int i = beg + j0; i < end; i += 8) {
        float lg = as_[csrsrc[i] * HEADS + h] + adv;
        lg = lg > 0.f ? lg : 0.2f * lg;
        alpha[(size_t)i * HEADS + h] = expf(lg - m) * inv;
    }
}

// ---------------- aggregation: block per node, thread per channel ----------------
__global__ void agg_csr(const int* __restrict__ rowptr, const int* __restrict__ csrsrc,
                        const float* __restrict__ alpha, const float* __restrict__ xh,
                        float* __restrict__ out, int M, int Cper) {
    int n = blockIdx.x;
    int c = threadIdx.x;
    if (c >= M) return;
    int h = c / Cper;
    int beg = rowptr[n], end = rowptr[n + 1];
    float acc = 0.f;
    for (int i = beg; i < end; i++) {
        float a = alpha[(size_t)i * HEADS + h];
        acc += a * xh[(size_t)csrsrc[i] * M + c];
    }
    out[(size_t)n * M + c] = acc;
}

// ---------------- finalize kernels (fused with next layer's A' conversion) ----------------
__global__ void final1(const float* __restrict__ agg, const float* __restrict__ b1,
                       const float* __restrict__ lin, const float* __restrict__ lin1b,
                       float* __restrict__ h, __nv_bfloat16* __restrict__ Ap) {
    long i = blockIdx.x * (long)blockDim.x + threadIdx.x;
    if (i >= (long)NN * M1) return;
    int n = (int)(i / M1), j = (int)(i % M1);
    float v = agg[i] + b1[j] + lin[i] + lin1b[j];
    v = v > 0.f ? v : expm1f(v);
    h[i] = v;
    __nv_bfloat16 hi = __float2bfloat16(v);
    __nv_bfloat16 lo = __float2bfloat16(v - __bfloat162float(hi));
    __nv_bfloat16* row = Ap + (size_t)n * 768;
    row[j] = hi; row[256 + j] = hi; row[512 + j] = lo;
}
__global__ void final2(const float* __restrict__ agg, const float* __restrict__ b2,
                       float* __restrict__ h, __nv_bfloat16* __restrict__ Ap) {
    long i = blockIdx.x * (long)blockDim.x + threadIdx.x;
    if (i >= (long)NN * M1) return;
    int n = (int)(i / M1), j = (int)(i % M1);
    float v = agg[i] + b2[j] + h[i];
    v = v > 0.f ? v : expm1f(v);
    h[i] = v;
    __nv_bfloat16 hi = __float2bfloat16(v);
    __nv_bfloat16 lo = __float2bfloat16(v - __bfloat162float(hi));
    __nv_bfloat16* row = Ap + (size_t)n * 768;
    row[j] = hi; row[256 + j] = hi; row[512 + j] = lo;
}
__global__ void final3(const float* __restrict__ agg, const float* __restrict__ b3,
                       const float* __restrict__ lin, const float* __restrict__ lin3b,
                       float* __restrict__ out) {
    long i = blockIdx.x * (long)blockDim.x + threadIdx.x;
    if (i >= (long)NN * NCLS) return;
    int n = (int)(i / NCLS), k = (int)(i % NCLS);
    const float* ar = agg + (size_t)n * M3;
    float s = 0.25f * (ar[k] + ar[NCLS + k] + ar[2 * NCLS + k] + ar[3 * NCLS + k]);
    out[i] = s + b3[k] + lin[i] + lin3b[k];
}

// ---------------- host orchestration ----------------
static void launch_gemm(const __nv_bfloat16* Ap, const __nv_bfloat16* Bp, float* C,
                        int Nrows, int Kp, int Nout) {
    dim3 gg((Nout + 127) / 128, (Nrows + 127) / 128);
    gemm_mma<<<gg, 256>>>(Ap, Bp, C, Nrows, Kp, Nout);
}

static void edge_softmax_agg(const int* rowptr, const int* csrsrc, const float* xh,
                             int H, int C, float* agg, float* as_, float* ad_, float* alpha,
                             const float* asrc, const float* adst) {
    int M = H * C;
    alpha_kernel<<<(NN * H * 32 + 255) / 256, 256>>>(xh, asrc, adst, as_, ad_, H, C);
    softmax_csr<<<(NN * 32 + 255) / 256, 256>>>(rowptr, csrsrc, as_, ad_, alpha);
    int bdim = (M + 31) & ~31;
    agg_csr<<<NN, bdim>>>(rowptr, csrsrc, alpha, xh, agg, M, C);
}

extern "C" void kernel_launch(void* const* d_in, const int* in_sizes, int n_in,
                              void* d_out, int out_size) {
    const float* x      = (const float*)d_in[0];
    const int*   ei     = (const int*)  d_in[1];
    const float* W1     = (const float*)d_in[2];
    const float* a1s    = (const float*)d_in[3];
    const float* a1d    = (const float*)d_in[4];
    const float* b1     = (const float*)d_in[5];
    const float* lin1W  = (const float*)d_in[6];
    const float* lin1b  = (const float*)d_in[7];
    const float* W2     = (const float*)d_in[8];
    const float* a2s    = (const float*)d_in[9];
    const float* a2d    = (const float*)d_in[10];
    const float* b2     = (const float*)d_in[11];
    const float* W3     = (const float*)d_in[12];
    const float* a3s    = (const float*)d_in[13];
    const float* a3d    = (const float*)d_in[14];
    const float* b3     = (const float*)d_in[15];
    const float* lin3W  = (const float*)d_in[16];
    const float* lin3b  = (const float*)d_in[17];
    float* out = (float*)d_out;

    float *xh, *agg, *lin, *h, *as_, *ad_, *alpha;
    __nv_bfloat16 *Ah, *Bt;
    int *deg, *rowptr, *cursor, *csrsrc;
    cudaGetSymbolAddress((void**)&xh,  g_xh);
    cudaGetSymbolAddress((void**)&agg, g_agg);
    cudaGetSymbolAddress((void**)&lin, g_lin);
    cudaGetSymbolAddress((void**)&h,   g_h);
    cudaGetSymbolAddress((void**)&as_, g_as);
    cudaGetSymbolAddress((void**)&ad_, g_ad);
    cudaGetSymbolAddress((void**)&alpha, g_alpha);
    cudaGetSymbolAddress((void**)&Ah,  g_Ah);
    cudaGetSymbolAddress((void**)&Bt,  g_Bt);
    cudaGetSymbolAddress((void**)&deg,    g_deg);
    cudaGetSymbolAddress((void**)&rowptr, g_rowptr);
    cudaGetSymbolAddress((void**)&cursor, g_cursor);
    cudaGetSymbolAddress((void**)&csrsrc, g_csrsrc);

    // ---- CSR build ----
    zero_i<<<(NN + 255) / 256, 256>>>(deg, NN);
    hist_dst<<<(EE + 255) / 256, 256>>>(ei, deg);
    scan_deg<<<1, 512>>>(deg, rowptr, cursor);
    scatter_csr<<<(EE + 255) / 256, 256>>>(ei, cursor, csrsrc);

    // ---- layer 1 ----
    convA<<<2048, 256>>>(x, Ah, NN, FIN);
    convB<<<(256 * FIN + 255) / 256, 256>>>(W1, Bt, FIN, M1, 256);
    launch_gemm(Ah, Bt, xh, NN, 3 * FIN, M1);
    edge_softmax_agg(rowptr, csrsrc, xh, HEADS, HID, agg, as_, ad_, alpha, a1s, a1d);
    convB<<<(256 * FIN + 255) / 256, 256>>>(lin1W, Bt, FIN, M1, 256);
    launch_gemm(Ah, Bt, lin, NN, 3 * FIN, M1);
    final1<<<((long)NN * M1 + 255) / 256, 256>>>(agg, b1, lin, lin1b, h, Ah);

    // ---- layer 2 ----
    convB<<<(256 * M1 + 255) / 256, 256>>>(W2, Bt, M1, M1, 256);
    launch_gemm(Ah, Bt, xh, NN, 3 * M1, M1);
    edge_softmax_agg(rowptr, csrsrc, xh, HEADS, HID, agg, as_, ad_, alpha, a2s, a2d);
    final2<<<((long)NN * M1 + 255) / 256, 256>>>(agg, b2, h, Ah);

    // ---- layer 3 ----
    convB<<<(512 * M1 + 255) / 256, 256>>>(W3, Bt, M1, M3, 512);
    launch_gemm(Ah, Bt, xh, NN, 3 * M1, M3);
    edge_softmax_agg(rowptr, csrsrc, xh, HEADS, NCLS, agg, as_, ad_, alpha, a3s, a3d);
    convB<<<(128 * M1 + 255) / 256, 256>>>(lin3W, Bt, M1, NCLS, 128);
    launch_gemm(Ah, Bt, lin, NN, 3 * M1, NCLS);
    final3<<<((long)NN * NCLS + 255) / 256, 256>>>(agg, b3, lin, lin3b, out);

    (void)in_sizes; (void)n_in; (void)out_size;
}

// round 7
// speedup vs baseline: 1.5266x; 1.0393x over previous
#include <cuda_runtime.h>
#include <cuda_fp16.h>
#include <math.h>
#include <stdint.h>

#define NN   50000
#define EE   400000
#define FIN  128
#define HID  64
#define HEADS 4
#define NCLS 121
#define M1   256   // HEADS*HID
#define M3   484   // OUT_HEADS*NCLS
#define NPAD 50048
#define P1   512   // L1 output pitch: [xh(256) | lin(256)]
#define P3   616   // L3 output pitch: [xh(484) | lin(121) | as(4) | ad(4)] = 613 used

// ---------------- scratch ----------------
__device__ float g_xh [(size_t)NN * P3];
__device__ float g_agg[(size_t)NN * M3];
__device__ float g_h  [(size_t)NN * M1];
__device__ float g_as [NN * HEADS];
__device__ float g_ad [NN * HEADS];
__device__ float g_wext[256 * 8];
__device__ __half g_Ah[(size_t)NPAD * 512];  // A' = [Xh | Xl], pitch 256 (L1) / 512 (L2,L3)
__device__ __half g_Bt[(size_t)640 * 512];   // B' = [Wh | Wh], per-layer widths
// CSR
__device__ int   g_deg   [NN];
__device__ int   g_rowptr[NN + 1];
__device__ int   g_cursor[NN];
__device__ int   g_csrsrc[EE];
__device__ float g_alpha [(size_t)EE * HEADS];

// ---------------- conversions (fp16 hi/lo, 2-term) ----------------
__global__ void convA(const float* __restrict__ X, __half* __restrict__ Ap, int Nrows, int K) {
    long i = blockIdx.x * (long)blockDim.x + threadIdx.x;
    long tot = (long)Nrows * K;
    long stride = (long)gridDim.x * blockDim.x;
    for (; i < tot; i += stride) {
        int r = (int)(i / K), k = (int)(i - (long)r * K);
        float x = X[i];
        __half h = __float2half_rn(x);
        __half l = __float2half_rn(x - __half2float(h));
        __half* row = Ap + (size_t)r * (2 * K);
        row[k] = h; row[K + k] = l;
    }
}
// B rows: [Wh | Wh]
__global__ void convB_W2(const float* __restrict__ W, __half* __restrict__ Bp) {
    int i = blockIdx.x * blockDim.x + threadIdx.x;   // n*K + k, K=256, Npad=256
    if (i >= 256 * 256) return;
    int n = i >> 8, k = i & 255;
    __half h = __float2half_rn(W[(size_t)k * 256 + n]);
    __half* row = Bp + (size_t)n * 512;
    row[k] = h; row[256 + k] = h;
}
__global__ void convB_L1(const float* __restrict__ W1, const float* __restrict__ linW,
                         __half* __restrict__ Bp) {
    int i = blockIdx.x * blockDim.x + threadIdx.x;   // n*K + k, K=128, Npad=512
    if (i >= 512 * 128) return;
    int n = i >> 7, k = i & 127;
    float w = (n < 256) ? W1[(size_t)k * 256 + n] : linW[(size_t)k * 256 + (n - 256)];
    __half h = __float2half_rn(w);
    __half* row = Bp + (size_t)n * 256;
    row[k] = h; row[128 + k] = h;
}
__global__ void wext_k(const float* __restrict__ W3, const float* __restrict__ a3s,
                       const float* __restrict__ a3d, float* __restrict__ wext) {
    int t = blockIdx.x * blockDim.x + threadIdx.x;   // k*8 + j
    if (t >= 256 * 8) return;
    int k = t >> 3, j = t & 7;
    int h = j & 3;
    const float* av = ((j >= 4) ? a3d : a3s) + h * NCLS;
    const float* wr = W3 + (size_t)k * M3 + h * NCLS;
    float s = 0.f;
    for (int c = 0; c < NCLS; c++) s += wr[c] * av[c];
    wext[k * 8 + j] = s;
}
__global__ void convB_L3(const float* __restrict__ W3, const float* __restrict__ linW,
                         const float* __restrict__ wext, __half* __restrict__ Bp) {
    int i = blockIdx.x * blockDim.x + threadIdx.x;   // n*K + k, K=256, Npad=640
    if (i >= 640 * 256) return;
    int n = i >> 8, k = i & 255;
    float w = 0.f;
    if (n < 484)      w = W3[(size_t)k * M3 + n];
    else if (n < 605) w = linW[(size_t)k * NCLS + (n - 484)];
    else if (n < 613) w = wext[k * 8 + (n - 605)];
    __half h = __float2half_rn(w);
    __half* row = Bp + (size_t)n * 512;
    row[k] = h; row[256 + k] = h;
}

// ---------------- pipelined HMMA fp16 GEMM ----------------
#define PITCH 80
#define STAGE_BYTES (128 * PITCH)
__global__ __launch_bounds__(256) void gemm_mma(const __half* __restrict__ A,
                                                const __half* __restrict__ Bt,
                                                float* __restrict__ C,
                                                int Nrows, int Kp, int Nout, int ldc) {
    __shared__ __align__(16) uint8_t smem[4 * STAGE_BYTES];
    uint32_t sbase = (uint32_t)__cvta_generic_to_shared(smem);

    int tid  = threadIdx.x;
    int wid  = tid >> 5, lane = tid & 31;
    int wm   = wid & 1;
    int wn   = wid >> 1;
    int g    = lane >> 2;
    int tg   = lane & 3;
    int rowBase = blockIdx.y * 128;
    int colBase = blockIdx.x * 128;

    int lrow = (lane & 7) + ((lane >> 3) & 1) * 8;
    int lcol = (lane >> 4) * 16;

    float acc[4][4][4];
#pragma unroll
    for (int i = 0; i < 4; i++)
#pragma unroll
        for (int j = 0; j < 4; j++)
#pragma unroll
            for (int q = 0; q < 4; q++) acc[i][j][q] = 0.f;

    int isB = tid >> 7;
    int lr  = tid & 127;
    const __half* gsrc = isB ? (Bt + (size_t)(colBase + lr) * Kp)
                             : (A  + (size_t)(rowBase + lr) * Kp);
    int niter = Kp >> 5;

    {
        uint32_t dst = sbase + (uint32_t)isB * STAGE_BYTES + lr * PITCH;
        const uint8_t* src = (const uint8_t*)(gsrc);
#pragma unroll
        for (int c = 0; c < 4; c++)
            asm volatile("cp.async.cg.shared.global [%0], [%1], 16;"
                         :: "r"(dst + c * 16), "l"(src + c * 16) : "memory");
        asm volatile("cp.async.commit_group;" ::: "memory");
    }

    for (int it = 0; it < niter; it++) {
        if (it + 1 < niter) {
            uint32_t dst = sbase + ((it + 1) & 1) * 2 * STAGE_BYTES + (uint32_t)isB * STAGE_BYTES + lr * PITCH;
            const uint8_t* src = (const uint8_t*)(gsrc + (it + 1) * 32);
#pragma unroll
            for (int c = 0; c < 4; c++)
                asm volatile("cp.async.cg.shared.global [%0], [%1], 16;"
                             :: "r"(dst + c * 16), "l"(src + c * 16) : "memory");
            asm volatile("cp.async.commit_group;" ::: "memory");
            asm volatile("cp.async.wait_group 1;" ::: "memory");
        } else {
            asm volatile("cp.async.wait_group 0;" ::: "memory");
        }
        __syncthreads();

        uint32_t sA = sbase + (it & 1) * 2 * STAGE_BYTES;
        uint32_t sB = sA + STAGE_BYTES;

#pragma unroll
        for (int ks = 0; ks < 2; ks++) {
            int kbyte = ks * 32;
            uint32_t a[4][4], b[2][4];
#pragma unroll
            for (int i = 0; i < 4; i++) {
                uint32_t addr = sA + (wm * 64 + i * 16 + lrow) * PITCH + kbyte + lcol;
                asm volatile("ldmatrix.sync.aligned.m8n8.x4.shared.b16 {%0,%1,%2,%3}, [%4];"
                             : "=r"(a[i][0]), "=r"(a[i][1]), "=r"(a[i][2]), "=r"(a[i][3]) : "r"(addr));
            }
#pragma unroll
            for (int p = 0; p < 2; p++) {
                uint32_t addr = sB + (wn * 32 + p * 16 + lrow) * PITCH + kbyte + lcol;
                asm volatile("ldmatrix.sync.aligned.m8n8.x4.shared.b16 {%0,%1,%2,%3}, [%4];"
                             : "=r"(b[p][0]), "=r"(b[p][1]), "=r"(b[p][2]), "=r"(b[p][3]) : "r"(addr));
            }
#pragma unroll
            for (int i = 0; i < 4; i++)
#pragma unroll
                for (int j = 0; j < 4; j++) {
                    uint32_t b0 = b[j >> 1][j & 1];
                    uint32_t b1 = b[j >> 1][2 + (j & 1)];
                    asm volatile(
                        "mma.sync.aligned.m16n8k16.row.col.f32.f16.f16.f32 "
                        "{%0,%1,%2,%3}, {%4,%5,%6,%7}, {%8,%9}, {%0,%1,%2,%3};"
                        : "+f"(acc[i][j][0]), "+f"(acc[i][j][1]), "+f"(acc[i][j][2]), "+f"(acc[i][j][3])
                        : "r"(a[i][0]), "r"(a[i][1]), "r"(a[i][2]), "r"(a[i][3]),
                          "r"(b0), "r"(b1));
                }
        }
        __syncthreads();
    }

#pragma unroll
    for (int i = 0; i < 4; i++) {
        int r0 = rowBase + wm * 64 + i * 16 + g;
#pragma unroll
        for (int j = 0; j < 4; j++) {
            int c0 = colBase + wn * 32 + j * 8 + tg * 2;
            if (r0 < Nrows) {
                if (c0     < Nout) C[(size_t)r0 * ldc + c0]     = acc[i][j][0];
                if (c0 + 1 < Nout) C[(size_t)r0 * ldc + c0 + 1] = acc[i][j][1];
            }
            if (r0 + 8 < Nrows) {
                if (c0     < Nout) C[(size_t)(r0 + 8) * ldc + c0]     = acc[i][j][2];
                if (c0 + 1 < Nout) C[(size_t)(r0 + 8) * ldc + c0 + 1] = acc[i][j][3];
            }
        }
    }
}

// ---------------- CSR construction ----------------
__global__ void zero_i(int* p, int n) {
    int i = blockIdx.x * blockDim.x + threadIdx.x;
    if (i < n) p[i] = 0;
}
__global__ void hist_dst(const int* __restrict__ ei, int* __restrict__ deg) {
    int e = blockIdx.x * blockDim.x + threadIdx.x;
    if (e < EE) atomicAdd(&deg[ei[EE + e]], 1);
}
__global__ void scan_deg(const int* __restrict__ deg, int* __restrict__ rowptr, int* __restrict__ cursor) {
    __shared__ int part[512];
    int t = threadIdx.x;
    const int CH = (NN + 511) / 512;
    int start = t * CH;
    int s = 0;
    for (int i = 0; i < CH; i++) {
        int idx = start + i;
        if (idx < NN) s += deg[idx];
    }
    part[t] = s;
    __syncthreads();
    for (int off = 1; off < 512; off <<= 1) {
        int v = (t >= off) ? part[t - off] : 0;
        __syncthreads();
        part[t] += v;
        __syncthreads();
    }
    int base = (t == 0) ? 0 : part[t - 1];
    for (int i = 0; i < CH; i++) {
        int idx = start + i;
        if (idx < NN) {
            rowptr[idx] = base;
            cursor[idx] = base;
            base += deg[idx];
        }
    }
    if (t == 511) rowptr[NN] = part[511];
}
__global__ void scatter_csr(const int* __restrict__ ei, int* __restrict__ cursor,
                            int* __restrict__ csrsrc) {
    int e = blockIdx.x * blockDim.x + threadIdx.x;
    if (e >= EE) return;
    int dst = ei[EE + e];
    int p = atomicAdd(&cursor[dst], 1);
    csrsrc[p] = ei[e];
}

// ---------------- alpha (layers 1,2) ----------------
__global__ void alpha_kernel(const float* __restrict__ xh, int pitch,
                             const float* __restrict__ asrc,
                             const float* __restrict__ adst,
                             float* __restrict__ as_, float* __restrict__ ad_,
                             int H, int C) {
    int w    = (blockIdx.x * blockDim.x + threadIdx.x) >> 5;
    int lane = threadIdx.x & 31;
    if (w >= NN * H) return;
    int n = w / H, h = w - n * H;
    const float* row = xh + (size_t)n * pitch + h * C;
    const float* w1  = asrc + h * C;
    const float* w2  = adst + h * C;
    float s1 = 0.f, s2 = 0.f;
    for (int c = lane; c < C; c += 32) {
        float v = row[c];
        s1 += v * w1[c];
        s2 += v * w2[c];
    }
#pragma unroll
    for (int o = 16; o; o >>= 1) {
        s1 += __shfl_down_sync(0xffffffffu, s1, o);
        s2 += __shfl_down_sync(0xffffffffu, s2, o);
    }
    if (lane == 0) { as_[w] = s1; ad_[w] = s2; }
}

// ---------------- per-node edge softmax (AS/AD with pitch, h stride 1) ----------------
__global__ void softmax_csr(const int* __restrict__ rowptr, const int* __restrict__ csrsrc,
                            const float* __restrict__ AS, const float* __restrict__ AD,
                            int pitch, float* __restrict__ alpha) {
    int w    = (blockIdx.x * blockDim.x + threadIdx.x) >> 5;
    int lane = threadIdx.x & 31;
    if (w >= NN) return;
    int h  = lane >> 3;
    int j0 = lane & 7;
    int beg = rowptr[w], end = rowptr[w + 1];
    float adv = AD[(size_t)w * pitch + h];
    float m = -INFINITY;
    for (int i = beg + j0; i < end; i += 8) {
        float lg = AS[(size_t)csrsrc[i] * pitch + h] + adv;
        lg = lg > 0.f ? lg : 0.2f * lg;
        m = fmaxf(m, lg);
    }
#pragma unroll
    for (int o = 1; o < 8; o <<= 1) m = fmaxf(m, __shfl_xor_sync(0xffffffffu, m, o));
    float den = 0.f;
    for (int i = beg + j0; i < end; i += 8) {
        float lg = AS[(size_t)csrsrc[i] * pitch + h] + adv;
        lg = lg > 0.f ? lg : 0.2f * lg;
        den += expf(lg - m);
    }
#pragma unroll
    for (int o = 1; o < 8; o <<= 1) den += __shfl_xor_sync(0xffffffffu, den, o);
    float inv = 1.f / (den + 1e-16f);
    for (int i = beg + j0; i < end; i += 8) {
        float lg = AS[(size_t)csrsrc[i] * pitch + h] + adv;
        lg = lg > 0.f ? lg : 0.2f * lg;
        alpha[(size_t)i * HEADS + h] = expf(lg - m) * inv;
    }
}

// ---------------- aggregation ----------------
__global__ void agg_csr(const int* __restrict__ rowptr, const int* __restrict__ csrsrc,
                        const float* __restrict__ alpha, const float* __restrict__ xh,
                        int pitch, float* __restrict__ out, int M, int Cper) {
    int n = blockIdx.x;
    int c = threadIdx.x;
    if (c >= M) return;
    int h = c / Cper;
    int beg = rowptr[n], end = rowptr[n + 1];
    float acc = 0.f;
    for (int i = beg; i < end; i++) {
        float a = alpha[(size_t)i * HEADS + h];
        acc += a * xh[(size_t)csrsrc[i] * pitch + c];
    }
    out[(size_t)n * M + c] = acc;
}

// ---------------- finals (fused next-layer A' conversion) ----------------
__global__ void final1(const float* __restrict__ agg, const float* __restrict__ b1,
                       const float* __restrict__ xh, const float* __restrict__ lin1b,
                       float* __restrict__ h, __half* __restrict__ Ap) {
    long i = blockIdx.x * (long)blockDim.x + threadIdx.x;
    if (i >= (long)NN * M1) return;
    int n = (int)(i / M1), j = (int)(i % M1);
    float v = agg[i] + b1[j] + xh[(size_t)n * P1 + 256 + j] + lin1b[j];
    v = v > 0.f ? v : expm1f(v);
    h[i] = v;
    __half hi = __float2half_rn(v);
    __half lo = __float2half_rn(v - __half2float(hi));
    __half* row = Ap + (size_t)n * 512;
    row[j] = hi; row[256 + j] = lo;
}
__global__ void final2(const float* __restrict__ agg, const float* __restrict__ b2,
                       float* __restrict__ h, __half* __restrict__ Ap) {
    long i = blockIdx.x * (long)blockDim.x + threadIdx.x;
    if (i >= (long)NN * M1) return;
    int n = (int)(i / M1), j = (int)(i % M1);
    float v = agg[i] + b2[j] + h[i];
    v = v > 0.f ? v : expm1f(v);
    h[i] = v;
    __half hi = __float2half_rn(v);
    __half lo = __float2half_rn(v - __half2float(hi));
    __half* row = Ap + (size_t)n * 512;
    row[j] = hi; row[256 + j] = lo;
}
__global__ void final3(const float* __restrict__ agg, const float* __restrict__ b3,
                       const float* __restrict__ xh, const float* __restrict__ lin3b,
                       float* __restrict__ out) {
    long i = blockIdx.x * (long)blockDim.x + threadIdx.x;
    if (i >= (long)NN * NCLS) return;
    int n = (int)(i / NCLS), k = (int)(i % NCLS);
    const float* ar = agg + (size_t)n * M3;
    float s = 0.25f * (ar[k] + ar[NCLS + k] + ar[2 * NCLS + k] + ar[3 * NCLS + k]);
    out[i] = s + b3[k] + xh[(size_t)n * P3 + 484 + k] + lin3b[k];
}

// ---------------- host ----------------
static void launch_gemm(const __half* Ap, const __half* Bp, float* C,
                        int Nrows, int Kp, int Nout, int ldc) {
    dim3 gg((Nout + 127) / 128, (Nrows + 127) / 128);
    gemm_mma<<<gg, 256>>>(Ap, Bp, C, Nrows, Kp, Nout, ldc);
}

extern "C" void kernel_launch(void* const* d_in, const int* in_sizes, int n_in,
                              void* d_out, int out_size) {
    const float* x      = (const float*)d_in[0];
    const int*   ei     = (const int*)  d_in[1];
    const float* W1     = (const float*)d_in[2];
    const float* a1s    = (const float*)d_in[3];
    const float* a1d    = (const float*)d_in[4];
    const float* b1     = (const float*)d_in[5];
    const float* lin1W  = (const float*)d_in[6];
    const float* lin1b  = (const float*)d_in[7];
    const float* W2     = (const float*)d_in[8];
    const float* a2s    = (const float*)d_in[9];
    const float* a2d    = (const float*)d_in[10];
    const float* b2     = (const float*)d_in[11];
    const float* W3     = (const float*)d_in[12];
    const float* a3s    = (const float*)d_in[13];
    const float* a3d    = (const float*)d_in[14];
    const float* b3     = (const float*)d_in[15];
    const float* lin3W  = (const float*)d_in[16];
    const float* lin3b  = (const float*)d_in[17];
    float* out = (float*)d_out;

    float *xh, *agg, *h, *as_, *ad_, *alpha, *wext;
    __half *Ah, *Bt;
    int *deg, *rowptr, *cursor, *csrsrc;
    cudaGetSymbolAddress((void**)&xh,  g_xh);
    cudaGetSymbolAddress((void**)&agg, g_agg);
    cudaGetSymbolAddress((void**)&h,   g_h);
    cudaGetSymbolAddress((void**)&as_, g_as);
    cudaGetSymbolAddress((void**)&ad_, g_ad);
    cudaGetSymbolAddress((void**)&alpha, g_alpha);
    cudaGetSymbolAddress((void**)&wext, g_wext);
    cudaGetSymbolAddress((void**)&Ah,  g_Ah);
    cudaGetSymbolAddress((void**)&Bt,  g_Bt);
    cudaGetSymbolAddress((void**)&deg,    g_deg);
    cudaGetSymbolAddress((void**)&rowptr, g_rowptr);
    cudaGetSymbolAddress((void**)&cursor, g_cursor);
    cudaGetSymbolAddress((void**)&csrsrc, g_csrsrc);

    // ---- CSR build ----
    zero_i<<<(NN + 255) / 256, 256>>>(deg, NN);
    hist_dst<<<(EE + 255) / 256, 256>>>(ei, deg);
    scan_deg<<<1, 512>>>(deg, rowptr, cursor);
    scatter_csr<<<(EE + 255) / 256, 256>>>(ei, cursor, csrsrc);

    // ---- layer 1: one GEMM for [xh | lin] ----
    convA<<<2048, 256>>>(x, Ah, NN, FIN);
    convB_L1<<<(512 * 128 + 255) / 256, 256>>>(W1, lin1W, Bt);
    launch_gemm(Ah, Bt, xh, NN, 256, 512, P1);
    alpha_kernel<<<(NN * HEADS * 32 + 255) / 256, 256>>>(xh, P1, a1s, a1d, as_, ad_, HEADS, HID);
    softmax_csr<<<(NN * 32 + 255) / 256, 256>>>(rowptr, csrsrc, as_, ad_, HEADS, alpha);
    agg_csr<<<NN, 256>>>(rowptr, csrsrc, alpha, xh, P1, agg, M1, HID);
    final1<<<((long)NN * M1 + 255) / 256, 256>>>(agg, b1, xh, lin1b, h, Ah);

    // ---- layer 2 ----
    convB_W2<<<(256 * 256 + 255) / 256, 256>>>(W2, Bt);
    launch_gemm(Ah, Bt, xh, NN, 512, 256, 256);
    alpha_kernel<<<(NN * HEADS * 32 + 255) / 256, 256>>>(xh, 256, a2s, a2d, as_, ad_, HEADS, HID);
    softmax_csr<<<(NN * 32 + 255) / 256, 256>>>(rowptr, csrsrc, as_, ad_, HEADS, alpha);
    agg_csr<<<NN, 256>>>(rowptr, csrsrc, alpha, xh, 256, agg, M1, HID);
    final2<<<((long)NN * M1 + 255) / 256, 256>>>(agg, b2, h, Ah);

    // ---- layer 3: one GEMM for [xh | lin | as | ad] ----
    wext_k<<<(256 * 8 + 255) / 256, 256>>>(W3, a3s, a3d, wext);
    convB_L3<<<(640 * 256 + 255) / 256, 256>>>(W3, lin3W, wext, Bt);
    launch_gemm(Ah, Bt, xh, NN, 512, 613, P3);
    softmax_csr<<<(NN * 32 + 255) / 256, 256>>>(rowptr, csrsrc, xh + 605, xh + 609, P3, alpha);
    agg_csr<<<NN, 512>>>(rowptr, csrsrc, alpha, xh, P3, agg, M3, NCLS);
    final3<<<((long)NN * NCLS + 255) / 256, 256>>>(agg, b3, xh, lin3b, out);

    (void)in_sizes; (void)n_in; (void)out_size;
}

// round 8
// speedup vs baseline: 1.7384x; 1.1388x over previous
#include <cuda_runtime.h>
#include <cuda_fp16.h>
#include <math.h>
#include <stdint.h>

#define NN   50000
#define EE   400000
#define FIN  128
#define HID  64
#define HEADS 4
#define NCLS 121
#define M1   256
#define M3   484
#define NPAD 50048
#define P1   512   // L1 gemm out pitch: [xh(256) | lin(256)]
#define P3   616   // L3 gemm out pitch: [xh(484) | lin(121) | as(4) | ad(4)]

// ---------------- scratch ----------------
__device__ float g_xh [(size_t)NN * P3];
__device__ float g_h  [(size_t)NN * M1];
__device__ float g_as [NN * HEADS];
__device__ float g_ad [NN * HEADS];
__device__ float g_wext[256 * 8];
__device__ __half g_Ah[(size_t)NPAD * 512];
__device__ __half g_Bt[(size_t)640 * 512];
__device__ int   g_deg   [NN];
__device__ int   g_rowptr[NN + 1];
__device__ int   g_cursor[NN];
__device__ int   g_csrsrc[EE];
__device__ float g_alpha [(size_t)EE * HEADS];

// ---------------- conversions ----------------
__global__ void convA(const float* __restrict__ X, __half* __restrict__ Ap, int Nrows, int K) {
    long i = blockIdx.x * (long)blockDim.x + threadIdx.x;
    long tot = (long)Nrows * K;
    long stride = (long)gridDim.x * blockDim.x;
    for (; i < tot; i += stride) {
        int r = (int)(i / K), k = (int)(i - (long)r * K);
        float x = X[i];
        __half h = __float2half_rn(x);
        __half l = __float2half_rn(x - __half2float(h));
        __half* row = Ap + (size_t)r * (2 * K);
        row[k] = h; row[K + k] = l;
    }
}
__global__ void convB_W2(const float* __restrict__ W, __half* __restrict__ Bp) {
    int i = blockIdx.x * blockDim.x + threadIdx.x;
    if (i >= 256 * 256) return;
    int n = i >> 8, k = i & 255;
    __half h = __float2half_rn(W[(size_t)k * 256 + n]);
    __half* row = Bp + (size_t)n * 512;
    row[k] = h; row[256 + k] = h;
}
__global__ void convB_L1(const float* __restrict__ W1, const float* __restrict__ linW,
                         __half* __restrict__ Bp) {
    int i = blockIdx.x * blockDim.x + threadIdx.x;
    if (i >= 512 * 128) return;
    int n = i >> 7, k = i & 127;
    float w = (n < 256) ? W1[(size_t)k * 256 + n] : linW[(size_t)k * 256 + (n - 256)];
    __half h = __float2half_rn(w);
    __half* row = Bp + (size_t)n * 256;
    row[k] = h; row[128 + k] = h;
}
__global__ void wext_k(const float* __restrict__ W3, const float* __restrict__ a3s,
                       const float* __restrict__ a3d, float* __restrict__ wext) {
    int t = blockIdx.x * blockDim.x + threadIdx.x;
    if (t >= 256 * 8) return;
    int k = t >> 3, j = t & 7;
    int h = j & 3;
    const float* av = ((j >= 4) ? a3d : a3s) + h * NCLS;
    const float* wr = W3 + (size_t)k * M3 + h * NCLS;
    float s = 0.f;
    for (int c = 0; c < NCLS; c++) s += wr[c] * av[c];
    wext[k * 8 + j] = s;
}
__global__ void convB_L3(const float* __restrict__ W3, const float* __restrict__ linW,
                         const float* __restrict__ wext, __half* __restrict__ Bp) {
    int i = blockIdx.x * blockDim.x + threadIdx.x;
    if (i >= 640 * 256) return;
    int n = i >> 8, k = i & 255;
    float w = 0.f;
    if (n < 484)      w = W3[(size_t)k * M3 + n];
    else if (n < 605) w = linW[(size_t)k * NCLS + (n - 484)];
    else if (n < 613) w = wext[k * 8 + (n - 605)];
    __half h = __float2half_rn(w);
    __half* row = Bp + (size_t)n * 512;
    row[k] = h; row[256 + k] = h;
}

// ---------------- pipelined HMMA fp16 GEMM (unchanged; ~fast enough) ----------------
#define PITCH 80
#define STAGE_BYTES (128 * PITCH)
__global__ __launch_bounds__(256) void gemm_mma(const __half* __restrict__ A,
                                                const __half* __restrict__ Bt,
                                                float* __restrict__ C,
                                                int Nrows, int Kp, int Nout, int ldc) {
    __shared__ __align__(16) uint8_t smem[4 * STAGE_BYTES];
    uint32_t sbase = (uint32_t)__cvta_generic_to_shared(smem);
    int tid  = threadIdx.x;
    int wid  = tid >> 5, lane = tid & 31;
    int wm   = wid & 1, wn = wid >> 1;
    int g    = lane >> 2, tg = lane & 3;
    int rowBase = blockIdx.y * 128;
    int colBase = blockIdx.x * 128;
    int lrow = (lane & 7) + ((lane >> 3) & 1) * 8;
    int lcol = (lane >> 4) * 16;

    float acc[4][4][4];
#pragma unroll
    for (int i = 0; i < 4; i++)
#pragma unroll
        for (int j = 0; j < 4; j++)
#pragma unroll
            for (int q = 0; q < 4; q++) acc[i][j][q] = 0.f;

    int isB = tid >> 7;
    int lr  = tid & 127;
    const __half* gsrc = isB ? (Bt + (size_t)(colBase + lr) * Kp)
                             : (A  + (size_t)(rowBase + lr) * Kp);
    int niter = Kp >> 5;
    {
        uint32_t dst = sbase + (uint32_t)isB * STAGE_BYTES + lr * PITCH;
        const uint8_t* src = (const uint8_t*)(gsrc);
#pragma unroll
        for (int c = 0; c < 4; c++)
            asm volatile("cp.async.cg.shared.global [%0], [%1], 16;"
                         :: "r"(dst + c * 16), "l"(src + c * 16) : "memory");
        asm volatile("cp.async.commit_group;" ::: "memory");
    }
    for (int it = 0; it < niter; it++) {
        if (it + 1 < niter) {
            uint32_t dst = sbase + ((it + 1) & 1) * 2 * STAGE_BYTES + (uint32_t)isB * STAGE_BYTES + lr * PITCH;
            const uint8_t* src = (const uint8_t*)(gsrc + (it + 1) * 32);
#pragma unroll
            for (int c = 0; c < 4; c++)
                asm volatile("cp.async.cg.shared.global [%0], [%1], 16;"
                             :: "r"(dst + c * 16), "l"(src + c * 16) : "memory");
            asm volatile("cp.async.commit_group;" ::: "memory");
            asm volatile("cp.async.wait_group 1;" ::: "memory");
        } else {
            asm volatile("cp.async.wait_group 0;" ::: "memory");
        }
        __syncthreads();
        uint32_t sA = sbase + (it & 1) * 2 * STAGE_BYTES;
        uint32_t sB = sA + STAGE_BYTES;
#pragma unroll
        for (int ks = 0; ks < 2; ks++) {
            int kbyte = ks * 32;
            uint32_t a[4][4], b[2][4];
#pragma unroll
            for (int i = 0; i < 4; i++) {
                uint32_t addr = sA + (wm * 64 + i * 16 + lrow) * PITCH + kbyte + lcol;
                asm volatile("ldmatrix.sync.aligned.m8n8.x4.shared.b16 {%0,%1,%2,%3}, [%4];"
                             : "=r"(a[i][0]), "=r"(a[i][1]), "=r"(a[i][2]), "=r"(a[i][3]) : "r"(addr));
            }
#pragma unroll
            for (int p = 0; p < 2; p++) {
                uint32_t addr = sB + (wn * 32 + p * 16 + lrow) * PITCH + kbyte + lcol;
                asm volatile("ldmatrix.sync.aligned.m8n8.x4.shared.b16 {%0,%1,%2,%3}, [%4];"
                             : "=r"(b[p][0]), "=r"(b[p][1]), "=r"(b[p][2]), "=r"(b[p][3]) : "r"(addr));
            }
#pragma unroll
            for (int i = 0; i < 4; i++)
#pragma unroll
                for (int j = 0; j < 4; j++) {
                    uint32_t b0 = b[j >> 1][j & 1];
                    uint32_t b1 = b[j >> 1][2 + (j & 1)];
                    asm volatile(
                        "mma.sync.aligned.m16n8k16.row.col.f32.f16.f16.f32 "
                        "{%0,%1,%2,%3}, {%4,%5,%6,%7}, {%8,%9}, {%0,%1,%2,%3};"
                        : "+f"(acc[i][j][0]), "+f"(acc[i][j][1]), "+f"(acc[i][j][2]), "+f"(acc[i][j][3])
                        : "r"(a[i][0]), "r"(a[i][1]), "r"(a[i][2]), "r"(a[i][3]),
                          "r"(b0), "r"(b1));
                }
        }
        __syncthreads();
    }
#pragma unroll
    for (int i = 0; i < 4; i++) {
        int r0 = rowBase + wm * 64 + i * 16 + g;
#pragma unroll
        for (int j = 0; j < 4; j++) {
            int c0 = colBase + wn * 32 + j * 8 + tg * 2;
            if (r0 < Nrows) {
                if (c0     < Nout) C[(size_t)r0 * ldc + c0]     = acc[i][j][0];
                if (c0 + 1 < Nout) C[(size_t)r0 * ldc + c0 + 1] = acc[i][j][1];
            }
            if (r0 + 8 < Nrows) {
                if (c0     < Nout) C[(size_t)(r0 + 8) * ldc + c0]     = acc[i][j][2];
                if (c0 + 1 < Nout) C[(size_t)(r0 + 8) * ldc + c0 + 1] = acc[i][j][3];
            }
        }
    }
}

// ---------------- CSR construction ----------------
__global__ void zero_i(int* p, int n) {
    int i = blockIdx.x * blockDim.x + threadIdx.x;
    if (i < n) p[i] = 0;
}
__global__ void hist_dst(const int* __restrict__ ei, int* __restrict__ deg) {
    int e = blockIdx.x * blockDim.x + threadIdx.x;
    if (e < EE) atomicAdd(&deg[ei[EE + e]], 1);
}
__global__ void scan_deg(const int* __restrict__ deg, int* __restrict__ rowptr, int* __restrict__ cursor) {
    __shared__ int part[512];
    int t = threadIdx.x;
    const int CH = (NN + 511) / 512;
    int start = t * CH;
    int s = 0;
    for (int i = 0; i < CH; i++) {
        int idx = start + i;
        if (idx < NN) s += deg[idx];
    }
    part[t] = s;
    __syncthreads();
    for (int off = 1; off < 512; off <<= 1) {
        int v = (t >= off) ? part[t - off] : 0;
        __syncthreads();
        part[t] += v;
        __syncthreads();
    }
    int base = (t == 0) ? 0 : part[t - 1];
    for (int i = 0; i < CH; i++) {
        int idx = start + i;
        if (idx < NN) {
            rowptr[idx] = base;
            cursor[idx] = base;
            base += deg[idx];
        }
    }
    if (t == 511) rowptr[NN] = part[511];
}
__global__ void scatter_csr(const int* __restrict__ ei, int* __restrict__ cursor,
                            int* __restrict__ csrsrc) {
    int e = blockIdx.x * blockDim.x + threadIdx.x;
    if (e >= EE) return;
    int dst = ei[EE + e];
    int p = atomicAdd(&cursor[dst], 1);
    csrsrc[p] = ei[e];
}

// ---------------- alpha (layers 1,2) ----------------
__global__ void alpha_kernel(const float* __restrict__ xh, int pitch,
                             const float* __restrict__ asrc,
                             const float* __restrict__ adst,
                             float* __restrict__ as_, float* __restrict__ ad_,
                             int H, int C) {
    int w    = (blockIdx.x * blockDim.x + threadIdx.x) >> 5;
    int lane = threadIdx.x & 31;
    if (w >= NN * H) return;
    int n = w / H, h = w - n * H;
    const float* row = xh + (size_t)n * pitch + h * C;
    const float* w1  = asrc + h * C;
    const float* w2  = adst + h * C;
    float s1 = 0.f, s2 = 0.f;
    for (int c = lane; c < C; c += 32) {
        float v = row[c];
        s1 += v * w1[c];
        s2 += v * w2[c];
    }
#pragma unroll
    for (int o = 16; o; o >>= 1) {
        s1 += __shfl_down_sync(0xffffffffu, s1, o);
        s2 += __shfl_down_sync(0xffffffffu, s2, o);
    }
    if (lane == 0) { as_[w] = s1; ad_[w] = s2; }
}

// ---------------- softmax: pass1 caches logits in alpha buffer, passes 2-3 stream ----------------
__global__ void softmax_csr(const int* __restrict__ rowptr, const int* __restrict__ csrsrc,
                            const float* __restrict__ AS, const float* __restrict__ AD,
                            int pitch, float* __restrict__ alpha) {
    int w    = (blockIdx.x * blockDim.x + threadIdx.x) >> 5;
    int lane = threadIdx.x & 31;
    if (w >= NN) return;
    int h  = lane >> 3;
    int j0 = lane & 7;
    int beg = rowptr[w], end = rowptr[w + 1];
    float adv = AD[(size_t)w * pitch + h];
    // pass 1: gather + leaky, cache logit (coalesced write: 32 lanes = 8 edges x 4 heads)
    float m = -INFINITY;
    for (int i = beg + j0; i < end; i += 8) {
        float lg = AS[(size_t)csrsrc[i] * pitch + h] + adv;
        lg = lg > 0.f ? lg : 0.2f * lg;
        alpha[(size_t)i * HEADS + h] = lg;
        m = fmaxf(m, lg);
    }
#pragma unroll
    for (int o = 1; o < 8; o <<= 1) m = fmaxf(m, __shfl_xor_sync(0xffffffffu, m, o));
    // pass 2: contiguous read
    float den = 0.f;
    for (int i = beg + j0; i < end; i += 8)
        den += expf(alpha[(size_t)i * HEADS + h] - m);
#pragma unroll
    for (int o = 1; o < 8; o <<= 1) den += __shfl_xor_sync(0xffffffffu, den, o);
    float inv = 1.f / (den + 1e-16f);
    // pass 3: contiguous read-modify-write
    for (int i = beg + j0; i < end; i += 8)
        alpha[(size_t)i * HEADS + h] = expf(alpha[(size_t)i * HEADS + h] - m) * inv;
}

// ---------------- fused aggregation + finalize ----------------
// 4-way unrolled edge loop for MLP; per-layer epilogues.
__device__ __forceinline__ float agg_acc(const int* __restrict__ rowptr,
                                         const int* __restrict__ csrsrc,
                                         const float* __restrict__ alpha,
                                         const float* __restrict__ xh,
                                         int pitch, int n, int c, int h) {
    int beg = rowptr[n], end = rowptr[n + 1];
    float acc = 0.f;
    int i = beg;
    for (; i + 3 < end; i += 4) {
        int s0 = csrsrc[i], s1 = csrsrc[i + 1], s2 = csrsrc[i + 2], s3 = csrsrc[i + 3];
        float a0 = alpha[(size_t)i * HEADS + h];
        float a1 = alpha[(size_t)(i + 1) * HEADS + h];
        float a2 = alpha[(size_t)(i + 2) * HEADS + h];
        float a3 = alpha[(size_t)(i + 3) * HEADS + h];
        float x0 = xh[(size_t)s0 * pitch + c];
        float x1 = xh[(size_t)s1 * pitch + c];
        float x2 = xh[(size_t)s2 * pitch + c];
        float x3 = xh[(size_t)s3 * pitch + c];
        acc += a0 * x0 + a1 * x1 + a2 * x2 + a3 * x3;
    }
    for (; i < end; i++)
        acc += alpha[(size_t)i * HEADS + h] * xh[(size_t)csrsrc[i] * pitch + c];
    return acc;
}

__global__ __launch_bounds__(256) void agg_final1(
        const int* __restrict__ rowptr, const int* __restrict__ csrsrc,
        const float* __restrict__ alpha, const float* __restrict__ xh,
        const float* __restrict__ b1, const float* __restrict__ lin1b,
        float* __restrict__ h_out, __half* __restrict__ Ap) {
    int n = blockIdx.x, c = threadIdx.x;
    float acc = agg_acc(rowptr, csrsrc, alpha, xh, P1, n, c, c >> 6);
    float v = acc + b1[c] + xh[(size_t)n * P1 + 256 + c] + lin1b[c];
    v = v > 0.f ? v : expm1f(v);
    h_out[(size_t)n * M1 + c] = v;
    __half hi = __float2half_rn(v);
    __half lo = __float2half_rn(v - __half2float(hi));
    __half* row = Ap + (size_t)n * 512;
    row[c] = hi; row[256 + c] = lo;
}

__global__ __launch_bounds__(256) void agg_final2(
        const int* __restrict__ rowptr, const int* __restrict__ csrsrc,
        const float* __restrict__ alpha, const float* __restrict__ xh,
        const float* __restrict__ b2,
        float* __restrict__ h_io, __half* __restrict__ Ap) {
    int n = blockIdx.x, c = threadIdx.x;
    float acc = agg_acc(rowptr, csrsrc, alpha, xh, 256, n, c, c >> 6);
    float v = acc + b2[c] + h_io[(size_t)n * M1 + c];
    v = v > 0.f ? v : expm1f(v);
    h_io[(size_t)n * M1 + c] = v;
    __half hi = __float2half_rn(v);
    __half lo = __float2half_rn(v - __half2float(hi));
    __half* row = Ap + (size_t)n * 512;
    row[c] = hi; row[256 + c] = lo;
}

__global__ __launch_bounds__(512) void agg_final3(
        const int* __restrict__ rowptr, const int* __restrict__ csrsrc,
        const float* __restrict__ alpha, const float* __restrict__ xh,
        const float* __restrict__ b3, const float* __restrict__ lin3b,
        float* __restrict__ out) {
    __shared__ float sm[M3];
    int n = blockIdx.x, c = threadIdx.x;
    if (c < M3) {
        sm[c] = agg_acc(rowptr, csrsrc, alpha, xh, P3, n, c, c / NCLS);
    }
    __syncthreads();
    if (c < NCLS) {
        float s = 0.25f * (sm[c] + sm[NCLS + c] + sm[2 * NCLS + c] + sm[3 * NCLS + c]);
        out[(size_t)n * NCLS + c] = s + b3[c] + xh[(size_t)n * P3 + 484 + c] + lin3b[c];
    }
}

// ---------------- host ----------------
static void launch_gemm(const __half* Ap, const __half* Bp, float* C,
                        int Nrows, int Kp, int Nout, int ldc) {
    dim3 gg((Nout + 127) / 128, (Nrows + 127) / 128);
    gemm_mma<<<gg, 256>>>(Ap, Bp, C, Nrows, Kp, Nout, ldc);
}

extern "C" void kernel_launch(void* const* d_in, const int* in_sizes, int n_in,
                              void* d_out, int out_size) {
    const float* x      = (const float*)d_in[0];
    const int*   ei     = (const int*)  d_in[1];
    const float* W1     = (const float*)d_in[2];
    const float* a1s    = (const float*)d_in[3];
    const float* a1d    = (const float*)d_in[4];
    const float* b1     = (const float*)d_in[5];
    const float* lin1W  = (const float*)d_in[6];
    const float* lin1b  = (const float*)d_in[7];
    const float* W2     = (const float*)d_in[8];
    const float* a2s    = (const float*)d_in[9];
    const float* a2d    = (const float*)d_in[10];
    const float* b2     = (const float*)d_in[11];
    const float* W3     = (const float*)d_in[12];
    const float* a3s    = (const float*)d_in[13];
    const float* a3d    = (const float*)d_in[14];
    const float* b3     = (const float*)d_in[15];
    const float* lin3W  = (const float*)d_in[16];
    const float* lin3b  = (const float*)d_in[17];
    float* out = (float*)d_out;

    float *xh, *h, *as_, *ad_, *alpha, *wext;
    __half *Ah, *Bt;
    int *deg, *rowptr, *cursor, *csrsrc;
    cudaGetSymbolAddress((void**)&xh,  g_xh);
    cudaGetSymbolAddress((void**)&h,   g_h);
    cudaGetSymbolAddress((void**)&as_, g_as);
    cudaGetSymbolAddress((void**)&ad_, g_ad);
    cudaGetSymbolAddress((void**)&alpha, g_alpha);
    cudaGetSymbolAddress((void**)&wext, g_wext);
    cudaGetSymbolAddress((void**)&Ah,  g_Ah);
    cudaGetSymbolAddress((void**)&Bt,  g_Bt);
    cudaGetSymbolAddress((void**)&deg,    g_deg);
    cudaGetSymbolAddress((void**)&rowptr, g_rowptr);
    cudaGetSymbolAddress((void**)&cursor, g_cursor);
    cudaGetSymbolAddress((void**)&csrsrc, g_csrsrc);

    // ---- CSR build ----
    zero_i<<<(NN + 255) / 256, 256>>>(deg, NN);
    hist_dst<<<(EE + 255) / 256, 256>>>(ei, deg);
    scan_deg<<<1, 512>>>(deg, rowptr, cursor);
    scatter_csr<<<(EE + 255) / 256, 256>>>(ei, cursor, csrsrc);

    // ---- layer 1 ----
    convA<<<2048, 256>>>(x, Ah, NN, FIN);
    convB_L1<<<(512 * 128 + 255) / 256, 256>>>(W1, lin1W, Bt);
    launch_gemm(Ah, Bt, xh, NN, 256, 512, P1);
    alpha_kernel<<<(NN * HEADS * 32 + 255) / 256, 256>>>(xh, P1, a1s, a1d, as_, ad_, HEADS, HID);
    softmax_csr<<<(NN * 32 + 255) / 256, 256>>>(rowptr, csrsrc, as_, ad_, HEADS, alpha);
    agg_final1<<<NN, 256>>>(rowptr, csrsrc, alpha, xh, b1, lin1b, h, Ah);

    // ---- layer 2 ----
    convB_W2<<<(256 * 256 + 255) / 256, 256>>>(W2, Bt);
    launch_gemm(Ah, Bt, xh, NN, 512, 256, 256);
    alpha_kernel<<<(NN * HEADS * 32 + 255) / 256, 256>>>(xh, 256, a2s, a2d, as_, ad_, HEADS, HID);
    softmax_csr<<<(NN * 32 + 255) / 256, 256>>>(rowptr, csrsrc, as_, ad_, HEADS, alpha);
    agg_final2<<<NN, 256>>>(rowptr, csrsrc, alpha, xh, b2, h, Ah);

    // ---- layer 3 ----
    wext_k<<<(256 * 8 + 255) / 256, 256>>>(W3, a3s, a3d, wext);
    convB_L3<<<(640 * 256 + 255) / 256, 256>>>(W3, lin3W, wext, Bt);
    launch_gemm(Ah, Bt, xh, NN, 512, 613, P3);
    softmax_csr<<<(NN * 32 + 255) / 256, 256>>>(rowptr, csrsrc, xh + 605, xh + 609, P3, alpha);
    agg_final3<<<NN, 512>>>(rowptr, csrsrc, alpha, xh, b3, lin3b, out);

    (void)in_sizes; (void)n_in; (void)out_size;
}